// round 1
// baseline (speedup 1.0000x reference)
#include <cuda_runtime.h>
#include <cuda_bf16.h>
#include <math.h>

// Problem constants
#define B_  2
#define S_  4096
#define D_  768
#define H_  12
#define HD_ 64
#define MROWS (B_ * S_)        // 8192

// Scratch (device globals; no allocation allowed)
__device__ float g_q[B_ * H_ * S_ * HD_];     // [b][h][s][hd], pre-scaled by 1/8
__device__ float g_k[B_ * H_ * S_ * HD_];
__device__ float g_v[B_ * H_ * S_ * HD_];
__device__ float g_attn[B_ * S_ * D_];        // [b][s][h*HD+hd]

// ---------------------------------------------------------------------------
// GEMM: out = X @ W^T + bias.  X:[M,768] row-major, W:[768,768] row-major.
// BM=BN=128, BK=16, 256 threads, 8x8 per-thread microtile.
// Smem staged transposed ([k][m] / [k][n]) for vectorized conflict-light reads.
// ---------------------------------------------------------------------------
#define BM 128
#define BN 128
#define BK 16

// Fused QKV projection. blockIdx.z selects q/k/v. Output in head-split layout.
__global__ void __launch_bounds__(256) proj_qkv_kernel(
    const float* __restrict__ x_q, const float* __restrict__ x_k, const float* __restrict__ x_v,
    const float* __restrict__ Wq, const float* __restrict__ bq,
    const float* __restrict__ Wk, const float* __restrict__ bk,
    const float* __restrict__ Wv, const float* __restrict__ bv)
{
    const int z = blockIdx.z;
    const float* __restrict__ X    = (z == 0) ? x_q : ((z == 1) ? x_k : x_v);
    const float* __restrict__ W    = (z == 0) ? Wq  : ((z == 1) ? Wk  : Wv);
    const float* __restrict__ bias = (z == 0) ? bq  : ((z == 1) ? bk  : bv);
    float* __restrict__ out        = (z == 0) ? g_q : ((z == 1) ? g_k : g_v);
    const float oscale = (z == 0) ? 0.125f : 1.0f;   // fold 1/sqrt(64) into Q

    __shared__ float Xs[BK][BM];
    __shared__ float Ws[BK][BN];

    const int tid = threadIdx.x;
    const int tx = tid & 15;
    const int ty = tid >> 4;
    const int m0 = blockIdx.y * BM;
    const int n0 = blockIdx.x * BN;

    float c[8][8];
    #pragma unroll
    for (int i = 0; i < 8; i++)
        #pragma unroll
        for (int j = 0; j < 8; j++) c[i][j] = 0.0f;

    for (int k0 = 0; k0 < D_; k0 += BK) {
        // Load tiles (coalesced global float4, transposed scalar smem stores)
        #pragma unroll
        for (int r = 0; r < 2; r++) {
            int f  = tid + 256 * r;          // 0..511
            int m  = f >> 2;                 // 0..127
            int c4 = (f & 3) * 4;            // 0,4,8,12
            float4 xv = *(const float4*)&X[(size_t)(m0 + m) * D_ + k0 + c4];
            Xs[c4 + 0][m] = xv.x; Xs[c4 + 1][m] = xv.y;
            Xs[c4 + 2][m] = xv.z; Xs[c4 + 3][m] = xv.w;
            float4 wv = *(const float4*)&W[(size_t)(n0 + m) * D_ + k0 + c4];
            Ws[c4 + 0][m] = wv.x; Ws[c4 + 1][m] = wv.y;
            Ws[c4 + 2][m] = wv.z; Ws[c4 + 3][m] = wv.w;
        }
        __syncthreads();

        #pragma unroll
        for (int kk = 0; kk < BK; kk++) {
            float a[8], b[8];
            *(float4*)(a)     = *(const float4*)(&Xs[kk][ty * 8]);
            *(float4*)(a + 4) = *(const float4*)(&Xs[kk][ty * 8 + 4]);
            *(float4*)(b)     = *(const float4*)(&Ws[kk][tx * 8]);
            *(float4*)(b + 4) = *(const float4*)(&Ws[kk][tx * 8 + 4]);
            #pragma unroll
            for (int i = 0; i < 8; i++)
                #pragma unroll
                for (int j = 0; j < 8; j++)
                    c[i][j] = fmaf(a[i], b[j], c[i][j]);
        }
        __syncthreads();
    }

    // Epilogue: bias, scale, head-split scatter [b][h][s][hd]
    #pragma unroll
    for (int i = 0; i < 8; i++) {
        int m = m0 + ty * 8 + i;
        int bb = m >> 12;            // m / 4096
        int ss = m & 4095;
        #pragma unroll
        for (int j = 0; j < 8; j++) {
            int n  = n0 + tx * 8 + j;
            int hh = n >> 6;
            int hd = n & 63;
            float val = (c[i][j] + bias[n]) * oscale;
            out[(((size_t)bb * H_ + hh) * S_ + ss) * HD_ + hd] = val;
        }
    }
}

// Output projection: d_out = g_attn @ Wo^T + bo  (plain row-major out)
__global__ void __launch_bounds__(256) out_proj_kernel(
    const float* __restrict__ Wo, const float* __restrict__ bo,
    float* __restrict__ out)
{
    __shared__ float Xs[BK][BM];
    __shared__ float Ws[BK][BN];

    const int tid = threadIdx.x;
    const int tx = tid & 15;
    const int ty = tid >> 4;
    const int m0 = blockIdx.y * BM;
    const int n0 = blockIdx.x * BN;

    float c[8][8];
    #pragma unroll
    for (int i = 0; i < 8; i++)
        #pragma unroll
        for (int j = 0; j < 8; j++) c[i][j] = 0.0f;

    for (int k0 = 0; k0 < D_; k0 += BK) {
        #pragma unroll
        for (int r = 0; r < 2; r++) {
            int f  = tid + 256 * r;
            int m  = f >> 2;
            int c4 = (f & 3) * 4;
            float4 xv = *(const float4*)&g_attn[(size_t)(m0 + m) * D_ + k0 + c4];
            Xs[c4 + 0][m] = xv.x; Xs[c4 + 1][m] = xv.y;
            Xs[c4 + 2][m] = xv.z; Xs[c4 + 3][m] = xv.w;
            float4 wv = *(const float4*)&Wo[(size_t)(n0 + m) * D_ + k0 + c4];
            Ws[c4 + 0][m] = wv.x; Ws[c4 + 1][m] = wv.y;
            Ws[c4 + 2][m] = wv.z; Ws[c4 + 3][m] = wv.w;
        }
        __syncthreads();

        #pragma unroll
        for (int kk = 0; kk < BK; kk++) {
            float a[8], b[8];
            *(float4*)(a)     = *(const float4*)(&Xs[kk][ty * 8]);
            *(float4*)(a + 4) = *(const float4*)(&Xs[kk][ty * 8 + 4]);
            *(float4*)(b)     = *(const float4*)(&Ws[kk][tx * 8]);
            *(float4*)(b + 4) = *(const float4*)(&Ws[kk][tx * 8 + 4]);
            #pragma unroll
            for (int i = 0; i < 8; i++)
                #pragma unroll
                for (int j = 0; j < 8; j++)
                    c[i][j] = fmaf(a[i], b[j], c[i][j]);
        }
        __syncthreads();
    }

    #pragma unroll
    for (int i = 0; i < 8; i++) {
        int m = m0 + ty * 8 + i;
        #pragma unroll
        for (int j = 0; j < 8; j++) {
            int n = n0 + tx * 8 + j;
            out[(size_t)m * D_ + n] = c[i][j] + bo[n];
        }
    }
}

// ---------------------------------------------------------------------------
// Flash attention, causal, fp32. 64 q-rows per CTA, 64-key tiles.
// 256 threads (16x16), each owns a 4x4 of the 64x64 score/output tile.
// Smem: Qs (row-major), KPs (K stored transposed [k][n], later reused for P
// row-major), Vs (row-major [k][d]). Exactly 48KB.
// ---------------------------------------------------------------------------
__global__ void __launch_bounds__(256) attn_kernel()
{
    __shared__ float Qs[64 * 64];
    __shared__ float KPs[64 * 64];
    __shared__ float Vs[64 * 64];

    const int tid = threadIdx.x;
    const int tx = tid & 15;
    const int ty = tid >> 4;
    const int bh = blockIdx.y;          // 0..23
    const int bb = bh / H_;
    const int hh = bh % H_;
    const int qt = blockIdx.x;          // 0..63
    const int q0 = qt * 64;

    const float* __restrict__ qptr = g_q + ((size_t)bh * S_ + q0) * HD_;

    // Load Q tile (already scaled by 1/8), row-major [m][k]
    for (int f = tid; f < 64 * 16; f += 256) {
        int m  = f >> 4;
        int c4 = (f & 15) * 4;
        *(float4*)&Qs[m * 64 + c4] = *(const float4*)&qptr[m * 64 + c4];
    }

    float o[4][4];
    float mrun[4], lrun[4];
    #pragma unroll
    for (int i = 0; i < 4; i++) {
        mrun[i] = -1e30f; lrun[i] = 0.0f;
        #pragma unroll
        for (int j = 0; j < 4; j++) o[i][j] = 0.0f;
    }

    for (int jt = 0; jt <= qt; jt++) {
        const int k0 = jt * 64;
        const float* __restrict__ kptr = g_k + ((size_t)bh * S_ + k0) * HD_;
        const float* __restrict__ vptr = g_v + ((size_t)bh * S_ + k0) * HD_;

        __syncthreads();   // previous iteration done reading KPs/Vs (also orders Q load)
        for (int f = tid; f < 64 * 16; f += 256) {
            int n  = f >> 4;
            int c4 = (f & 15) * 4;
            float4 kv = *(const float4*)&kptr[n * 64 + c4];
            KPs[(c4 + 0) * 64 + n] = kv.x;
            KPs[(c4 + 1) * 64 + n] = kv.y;
            KPs[(c4 + 2) * 64 + n] = kv.z;
            KPs[(c4 + 3) * 64 + n] = kv.w;
            *(float4*)&Vs[n * 64 + c4] = *(const float4*)&vptr[n * 64 + c4];
        }
        __syncthreads();

        // S = Q @ K^T  (Q pre-scaled)
        float s[4][4];
        #pragma unroll
        for (int i = 0; i < 4; i++)
            #pragma unroll
            for (int j = 0; j < 4; j++) s[i][j] = 0.0f;

        #pragma unroll 8
        for (int kk = 0; kk < 64; kk++) {
            float a[4], b[4];
            #pragma unroll
            for (int i = 0; i < 4; i++) a[i] = Qs[(ty * 4 + i) * 64 + kk];
            *(float4*)b = *(const float4*)&KPs[kk * 64 + tx * 4];
            #pragma unroll
            for (int i = 0; i < 4; i++)
                #pragma unroll
                for (int j = 0; j < 4; j++)
                    s[i][j] = fmaf(a[i], b[j], s[i][j]);
        }

        // Causal mask (only diagonal tile has masked entries)
        if (jt == qt) {
            #pragma unroll
            for (int i = 0; i < 4; i++)
                #pragma unroll
                for (int j = 0; j < 4; j++)
                    if (k0 + tx * 4 + j > q0 + ty * 4 + i) s[i][j] = -1e30f;
        }

        // Online softmax update (row groups = 16 lanes sharing ty)
        #pragma unroll
        for (int i = 0; i < 4; i++) {
            float mt = fmaxf(fmaxf(s[i][0], s[i][1]), fmaxf(s[i][2], s[i][3]));
            #pragma unroll
            for (int off = 8; off >= 1; off >>= 1)
                mt = fmaxf(mt, __shfl_xor_sync(0xffffffffu, mt, off));
            float mnew  = fmaxf(mrun[i], mt);
            float scale = __expf(mrun[i] - mnew);
            float ps = 0.0f;
            #pragma unroll
            for (int j = 0; j < 4; j++) {
                s[i][j] = __expf(s[i][j] - mnew);
                ps += s[i][j];
            }
            #pragma unroll
            for (int off = 8; off >= 1; off >>= 1)
                ps += __shfl_xor_sync(0xffffffffu, ps, off);
            lrun[i] = lrun[i] * scale + ps;
            mrun[i] = mnew;
            #pragma unroll
            for (int j = 0; j < 4; j++) o[i][j] *= scale;
        }

        __syncthreads();   // all threads done reading KPs as K^T
        // Store P (row-major) into KPs
        #pragma unroll
        for (int i = 0; i < 4; i++)
            #pragma unroll
            for (int j = 0; j < 4; j++)
                KPs[(ty * 4 + i) * 64 + tx * 4 + j] = s[i][j];
        __syncthreads();

        // O += P @ V
        #pragma unroll 8
        for (int kk = 0; kk < 64; kk++) {
            float a[4], b[4];
            #pragma unroll
            for (int i = 0; i < 4; i++) a[i] = KPs[(ty * 4 + i) * 64 + kk];
            *(float4*)b = *(const float4*)&Vs[kk * 64 + tx * 4];
            #pragma unroll
            for (int i = 0; i < 4; i++)
                #pragma unroll
                for (int j = 0; j < 4; j++)
                    o[i][j] = fmaf(a[i], b[j], o[i][j]);
        }
    }

    // Normalize and write to [b][s][h*HD+hd]
    #pragma unroll
    for (int i = 0; i < 4; i++) {
        float inv = 1.0f / lrun[i];
        int srow = q0 + ty * 4 + i;
        #pragma unroll
        for (int j = 0; j < 4; j++) {
            g_attn[((size_t)bb * S_ + srow) * D_ + hh * HD_ + tx * 4 + j] = o[i][j] * inv;
        }
    }
}

// ---------------------------------------------------------------------------
extern "C" void kernel_launch(void* const* d_in, const int* in_sizes, int n_in,
                              void* d_out, int out_size)
{
    const float* query = (const float*)d_in[0];
    const float* key_  = (const float*)d_in[1];
    const float* value = (const float*)d_in[2];
    // d_in[3] = mask (tril) — handled analytically as causal
    const float* Wq = (const float*)d_in[4];
    const float* bq = (const float*)d_in[5];
    const float* Wk = (const float*)d_in[6];
    const float* bk = (const float*)d_in[7];
    const float* Wv = (const float*)d_in[8];
    const float* bv = (const float*)d_in[9];
    const float* Wo = (const float*)d_in[10];
    const float* bo = (const float*)d_in[11];
    float* out = (float*)d_out;

    dim3 gproj(D_ / BN, MROWS / BM, 3);        // (6, 64, 3)
    proj_qkv_kernel<<<gproj, 256>>>(query, key_, value, Wq, bq, Wk, bk, Wv, bv);

    dim3 gattn(S_ / 64, B_ * H_);              // (64, 24)
    attn_kernel<<<gattn, 256>>>();

    dim3 gout(D_ / BN, MROWS / BM);            // (6, 64)
    out_proj_kernel<<<gout, 256>>>(Wo, bo, out);
}

// round 2
// speedup vs baseline: 2.2733x; 2.2733x over previous
#include <cuda_runtime.h>
#include <cuda_bf16.h>
#include <math.h>
#include <stdint.h>

// Problem constants
#define B_  2
#define S_  4096
#define D_  768
#define H_  12
#define HD_ 64
#define MROWS (B_*S_)
#define NELEM (B_*H_*S_*HD_)

// Scratch: Q/K/V stored pre-split into bf16 hi/lo pairs, [b][h][s][hd]
__device__ __nv_bfloat16 g_qh[NELEM], g_ql[NELEM];
__device__ __nv_bfloat16 g_kh[NELEM], g_kl[NELEM];
__device__ __nv_bfloat16 g_vh[NELEM], g_vl[NELEM];
__device__ float g_attn[MROWS * D_];   // [b][s][h*HD+hd]

// ---------------------------------------------------------------------------
// helpers
// ---------------------------------------------------------------------------
__device__ __forceinline__ void split2(float x0, float x1, uint32_t& hi, uint32_t& lo) {
    __nv_bfloat16 h0 = __float2bfloat16(x0);
    __nv_bfloat16 h1 = __float2bfloat16(x1);
    __nv_bfloat16 l0 = __float2bfloat16(x0 - __bfloat162float(h0));
    __nv_bfloat16 l1 = __float2bfloat16(x1 - __bfloat162float(h1));
    hi = ((uint32_t)__bfloat16_as_ushort(h1) << 16) | (uint32_t)__bfloat16_as_ushort(h0);
    lo = ((uint32_t)__bfloat16_as_ushort(l1) << 16) | (uint32_t)__bfloat16_as_ushort(l0);
}

__device__ __forceinline__ void mma16816(float (&c)[4], const uint32_t (&a)[4],
                                         const uint32_t (&b)[2]) {
    asm volatile(
        "mma.sync.aligned.m16n8k16.row.col.f32.bf16.bf16.f32 "
        "{%0,%1,%2,%3}, {%4,%5,%6,%7}, {%8,%9}, {%0,%1,%2,%3};\n"
        : "+f"(c[0]), "+f"(c[1]), "+f"(c[2]), "+f"(c[3])
        : "r"(a[0]), "r"(a[1]), "r"(a[2]), "r"(a[3]), "r"(b[0]), "r"(b[1]));
}

// ---------------------------------------------------------------------------
// GEMM core: C = X @ W^T + bias. X:[8192,768], W:[768,768], both row-major.
// BM=BN=128, BK=32, 256 threads = 8 warps (4m x 2n), warp tile 32x64.
// bf16x3 split MMA. Smem rows padded to 20 words (conflict-free frag loads).
// MODE 0: epilogue scale + split + head-split scatter to (outh, outl)
// MODE 1: epilogue plain fp32 row-major to outf
// ---------------------------------------------------------------------------
#define SKW 20   // smem row stride in 32-bit words (= 40 bf16, 32 used)

template<int MODE>
__device__ __forceinline__ void gemm_core(
    const float* __restrict__ X, const float* __restrict__ W,
    const float* __restrict__ bias, float osc,
    __nv_bfloat16* __restrict__ outh, __nv_bfloat16* __restrict__ outl,
    float* __restrict__ outf)
{
    __shared__ __align__(16) uint32_t Ah[128 * SKW], Al[128 * SKW];
    __shared__ __align__(16) uint32_t Bh[128 * SKW], Bl[128 * SKW];

    const int tid  = threadIdx.x;
    const int lane = tid & 31;
    const int warp = tid >> 5;
    const int wm = warp >> 1;          // 0..3
    const int wn = warp & 1;           // 0..1
    const int g  = lane >> 2;
    const int t  = lane & 3;
    const int m0 = blockIdx.y * 128;
    const int n0 = blockIdx.x * 128;

    float c[2][8][4];
    #pragma unroll
    for (int fi = 0; fi < 2; fi++)
        #pragma unroll
        for (int fj = 0; fj < 8; fj++)
            #pragma unroll
            for (int e = 0; e < 4; e++) c[fi][fj][e] = 0.0f;

    float4 pa[4], pb[4];
    // prefetch tile 0
    #pragma unroll
    for (int p = 0; p < 4; p++) {
        int idx = p * 256 + tid;
        int r  = idx >> 3;
        int c4 = (idx & 7) * 4;
        pa[p] = *(const float4*)&X[(size_t)(m0 + r) * D_ + c4];
        pb[p] = *(const float4*)&W[(size_t)(n0 + r) * D_ + c4];
    }

    for (int kt = 0; kt < 24; kt++) {
        // stage prefetched tile into smem (split hi/lo)
        #pragma unroll
        for (int p = 0; p < 4; p++) {
            int idx = p * 256 + tid;
            int r  = idx >> 3;
            int c4 = (idx & 7) * 4;
            int w0 = r * SKW + (c4 >> 1);
            uint32_t h01, l01, h23, l23;
            split2(pa[p].x, pa[p].y, h01, l01);
            split2(pa[p].z, pa[p].w, h23, l23);
            Ah[w0] = h01; Ah[w0 + 1] = h23;
            Al[w0] = l01; Al[w0 + 1] = l23;
            split2(pb[p].x, pb[p].y, h01, l01);
            split2(pb[p].z, pb[p].w, h23, l23);
            Bh[w0] = h01; Bh[w0 + 1] = h23;
            Bl[w0] = l01; Bl[w0 + 1] = l23;
        }
        __syncthreads();

        if (kt < 23) {
            int k0n = (kt + 1) * 32;
            #pragma unroll
            for (int p = 0; p < 4; p++) {
                int idx = p * 256 + tid;
                int r  = idx >> 3;
                int c4 = (idx & 7) * 4;
                pa[p] = *(const float4*)&X[(size_t)(m0 + r) * D_ + k0n + c4];
                pb[p] = *(const float4*)&W[(size_t)(n0 + r) * D_ + k0n + c4];
            }
        }

        #pragma unroll
        for (int ks = 0; ks < 2; ks++) {
            uint32_t ah[2][4], al[2][4];
            #pragma unroll
            for (int fi = 0; fi < 2; fi++) {
                int base = (wm * 32 + fi * 16 + g) * SKW + ks * 8 + t;
                ah[fi][0] = Ah[base];
                ah[fi][1] = Ah[base + 8 * SKW];
                ah[fi][2] = Ah[base + 4];
                ah[fi][3] = Ah[base + 8 * SKW + 4];
                al[fi][0] = Al[base];
                al[fi][1] = Al[base + 8 * SKW];
                al[fi][2] = Al[base + 4];
                al[fi][3] = Al[base + 8 * SKW + 4];
            }
            #pragma unroll
            for (int fj = 0; fj < 8; fj++) {
                int bw = (wn * 64 + fj * 8 + g) * SKW + ks * 8 + t;
                uint32_t bhf[2] = { Bh[bw], Bh[bw + 4] };
                uint32_t blf[2] = { Bl[bw], Bl[bw + 4] };
                #pragma unroll
                for (int fi = 0; fi < 2; fi++) {
                    mma16816(c[fi][fj], ah[fi], bhf);
                    mma16816(c[fi][fj], ah[fi], blf);
                    mma16816(c[fi][fj], al[fi], bhf);
                }
            }
        }
        __syncthreads();
    }

    // epilogue
    #pragma unroll
    for (int fi = 0; fi < 2; fi++) {
        #pragma unroll
        for (int rr = 0; rr < 2; rr++) {
            int m = m0 + wm * 32 + fi * 16 + g + rr * 8;
            #pragma unroll
            for (int fj = 0; fj < 8; fj++) {
                int n = n0 + wn * 64 + fj * 8 + 2 * t;
                float v0 = c[fi][fj][rr * 2 + 0] + bias[n];
                float v1 = c[fi][fj][rr * 2 + 1] + bias[n + 1];
                if (MODE == 0) {
                    v0 *= osc; v1 *= osc;
                    int bb = m >> 12, ss = m & 4095;
                    int hh = n >> 6,  hd = n & 63;
                    size_t off = (((size_t)bb * H_ + hh) * S_ + ss) * HD_ + hd;
                    uint32_t hw, lw;
                    split2(v0, v1, hw, lw);
                    *(uint32_t*)&outh[off] = hw;
                    *(uint32_t*)&outl[off] = lw;
                } else {
                    float2 o2; o2.x = v0; o2.y = v1;
                    *(float2*)&outf[(size_t)m * D_ + n] = o2;
                }
            }
        }
    }
}

__global__ void __launch_bounds__(256) proj_qkv(
    const float* __restrict__ xq, const float* __restrict__ xk, const float* __restrict__ xv,
    const float* __restrict__ Wq, const float* __restrict__ bq,
    const float* __restrict__ Wk, const float* __restrict__ bk,
    const float* __restrict__ Wv, const float* __restrict__ bv)
{
    int z = blockIdx.z;
    const float* X    = (z == 0) ? xq : (z == 1) ? xk : xv;
    const float* W    = (z == 0) ? Wq : (z == 1) ? Wk : Wv;
    const float* bias = (z == 0) ? bq : (z == 1) ? bk : bv;
    __nv_bfloat16* oh = (z == 0) ? g_qh : (z == 1) ? g_kh : g_vh;
    __nv_bfloat16* ol = (z == 0) ? g_ql : (z == 1) ? g_kl : g_vl;
    float osc = (z == 0) ? 0.125f : 1.0f;   // fold 1/sqrt(64) into Q
    gemm_core<0>(X, W, bias, osc, oh, ol, nullptr);
}

__global__ void __launch_bounds__(256) proj_out(
    const float* __restrict__ Wo, const float* __restrict__ bo, float* __restrict__ out)
{
    gemm_core<1>(g_attn, Wo, bo, 1.0f, nullptr, nullptr, out);
}

// ---------------------------------------------------------------------------
// Flash attention, causal, bf16x3 MMA. 64 q-rows per CTA, 64-key tiles.
// 128 threads = 4 warps, each warp owns 16 q-rows x full 64 keys/HD.
// K smem [seq][hd], V smem transposed [hd][seq]; rows padded to 36 words.
// ---------------------------------------------------------------------------
__global__ void __launch_bounds__(128) attn_kernel()
{
    __shared__ __align__(16) __nv_bfloat16 Khs[64 * 72], Kls[64 * 72];
    __shared__ __align__(16) __nv_bfloat16 Vhs[64 * 72], Vls[64 * 72];
    uint32_t* Khw = (uint32_t*)Khs;
    uint32_t* Klw = (uint32_t*)Kls;
    uint32_t* Vhw = (uint32_t*)Vhs;
    uint32_t* Vlw = (uint32_t*)Vls;

    const int tid  = threadIdx.x;
    const int lane = tid & 31;
    const int wm   = tid >> 5;        // 0..3
    const int g    = lane >> 2;
    const int t    = lane & 3;
    const int qt = blockIdx.x;
    const int bh = blockIdx.y;
    const int bb = bh / H_;
    const int hh = bh % H_;
    const int q0 = qt * 64;

    // Q fragments (held in registers for whole CTA lifetime)
    uint32_t qh[4][4], ql[4][4];
    {
        const __nv_bfloat16* qb = g_qh + ((size_t)bh * S_ + q0 + wm * 16) * HD_;
        const __nv_bfloat16* qlb = g_ql + ((size_t)bh * S_ + q0 + wm * 16) * HD_;
        #pragma unroll
        for (int kt = 0; kt < 4; kt++) {
            int kc = kt * 16 + 2 * t;
            qh[kt][0] = *(const uint32_t*)&qb[(size_t)g * HD_ + kc];
            qh[kt][1] = *(const uint32_t*)&qb[(size_t)(g + 8) * HD_ + kc];
            qh[kt][2] = *(const uint32_t*)&qb[(size_t)g * HD_ + kc + 8];
            qh[kt][3] = *(const uint32_t*)&qb[(size_t)(g + 8) * HD_ + kc + 8];
            ql[kt][0] = *(const uint32_t*)&qlb[(size_t)g * HD_ + kc];
            ql[kt][1] = *(const uint32_t*)&qlb[(size_t)(g + 8) * HD_ + kc];
            ql[kt][2] = *(const uint32_t*)&qlb[(size_t)g * HD_ + kc + 8];
            ql[kt][3] = *(const uint32_t*)&qlb[(size_t)(g + 8) * HD_ + kc + 8];
        }
    }

    float o[8][4];
    float mrun[2], lrun[2];
    mrun[0] = mrun[1] = -1e30f;
    lrun[0] = lrun[1] = 0.0f;
    #pragma unroll
    for (int fj = 0; fj < 8; fj++)
        #pragma unroll
        for (int e = 0; e < 4; e++) o[fj][e] = 0.0f;

    const int r0 = q0 + wm * 16 + g;      // row of c0,c1
    const int r1 = r0 + 8;                // row of c2,c3

    for (int jt = 0; jt <= qt; jt++) {
        const int k0 = jt * 64;
        __syncthreads();   // previous iteration finished reading smem

        // load K/V tile (pre-split bf16 hi/lo from global)
        #pragma unroll
        for (int it = 0; it < 8; it++) {
            int f   = it * 128 + tid;
            int row = f >> 4;
            int c4  = (f & 15) * 4;
            size_t gofs = ((size_t)bh * S_ + k0 + row) * HD_ + c4;
            int w0 = row * 36 + (c4 >> 1);
            uint2 kh2 = *(const uint2*)&g_kh[gofs];
            uint2 kl2 = *(const uint2*)&g_kl[gofs];
            Khw[w0] = kh2.x; Khw[w0 + 1] = kh2.y;
            Klw[w0] = kl2.x; Klw[w0 + 1] = kl2.y;
            uint2 vh2 = *(const uint2*)&g_vh[gofs];
            uint2 vl2 = *(const uint2*)&g_vl[gofs];
            __nv_bfloat162 a0 = *(__nv_bfloat162*)&vh2.x;
            __nv_bfloat162 a1 = *(__nv_bfloat162*)&vh2.y;
            Vhs[(c4 + 0) * 72 + row] = a0.x;
            Vhs[(c4 + 1) * 72 + row] = a0.y;
            Vhs[(c4 + 2) * 72 + row] = a1.x;
            Vhs[(c4 + 3) * 72 + row] = a1.y;
            __nv_bfloat162 b0 = *(__nv_bfloat162*)&vl2.x;
            __nv_bfloat162 b1 = *(__nv_bfloat162*)&vl2.y;
            Vls[(c4 + 0) * 72 + row] = b0.x;
            Vls[(c4 + 1) * 72 + row] = b0.y;
            Vls[(c4 + 2) * 72 + row] = b1.x;
            Vls[(c4 + 3) * 72 + row] = b1.y;
        }
        __syncthreads();

        // S = Q @ K^T
        float s[8][4];
        #pragma unroll
        for (int fj = 0; fj < 8; fj++)
            #pragma unroll
            for (int e = 0; e < 4; e++) s[fj][e] = 0.0f;

        #pragma unroll
        for (int kt = 0; kt < 4; kt++) {
            #pragma unroll
            for (int fj = 0; fj < 8; fj++) {
                int bw = (fj * 8 + g) * 36 + kt * 8 + t;
                uint32_t bhf[2] = { Khw[bw], Khw[bw + 4] };
                uint32_t blf[2] = { Klw[bw], Klw[bw + 4] };
                mma16816(s[fj], qh[kt], bhf);
                mma16816(s[fj], qh[kt], blf);
                mma16816(s[fj], ql[kt], bhf);
            }
        }

        // causal mask on diagonal tile
        if (jt == qt) {
            #pragma unroll
            for (int fj = 0; fj < 8; fj++) {
                int cn = k0 + fj * 8 + 2 * t;
                if (cn     > r0) s[fj][0] = -1e30f;
                if (cn + 1 > r0) s[fj][1] = -1e30f;
                if (cn     > r1) s[fj][2] = -1e30f;
                if (cn + 1 > r1) s[fj][3] = -1e30f;
            }
        }

        // online softmax (row stats within thread quad via shfl)
        #pragma unroll
        for (int r = 0; r < 2; r++) {
            float mx = -1e30f;
            #pragma unroll
            for (int fj = 0; fj < 8; fj++)
                mx = fmaxf(mx, fmaxf(s[fj][2 * r], s[fj][2 * r + 1]));
            mx = fmaxf(mx, __shfl_xor_sync(0xffffffffu, mx, 1));
            mx = fmaxf(mx, __shfl_xor_sync(0xffffffffu, mx, 2));
            float mnew  = fmaxf(mrun[r], mx);
            float scale = __expf(mrun[r] - mnew);
            float sum = 0.0f;
            #pragma unroll
            for (int fj = 0; fj < 8; fj++) {
                float p0 = __expf(s[fj][2 * r]     - mnew);
                float p1 = __expf(s[fj][2 * r + 1] - mnew);
                s[fj][2 * r] = p0; s[fj][2 * r + 1] = p1;
                sum += p0 + p1;
            }
            sum += __shfl_xor_sync(0xffffffffu, sum, 1);
            sum += __shfl_xor_sync(0xffffffffu, sum, 2);
            lrun[r] = lrun[r] * scale + sum;
            mrun[r] = mnew;
            #pragma unroll
            for (int fj = 0; fj < 8; fj++) {
                o[fj][2 * r]     *= scale;
                o[fj][2 * r + 1] *= scale;
            }
        }

        // pack P into A-fragments (hi/lo split)
        uint32_t ph[4][4], pl[4][4];
        #pragma unroll
        for (int k2 = 0; k2 < 4; k2++) {
            split2(s[2 * k2][0],     s[2 * k2][1],     ph[k2][0], pl[k2][0]);
            split2(s[2 * k2][2],     s[2 * k2][3],     ph[k2][1], pl[k2][1]);
            split2(s[2 * k2 + 1][0], s[2 * k2 + 1][1], ph[k2][2], pl[k2][2]);
            split2(s[2 * k2 + 1][2], s[2 * k2 + 1][3], ph[k2][3], pl[k2][3]);
        }

        // O += P @ V
        #pragma unroll
        for (int k2 = 0; k2 < 4; k2++) {
            #pragma unroll
            for (int fj = 0; fj < 8; fj++) {
                int bw = (fj * 8 + g) * 36 + k2 * 8 + t;
                uint32_t bhf[2] = { Vhw[bw], Vhw[bw + 4] };
                uint32_t blf[2] = { Vlw[bw], Vlw[bw + 4] };
                mma16816(o[fj], ph[k2], bhf);
                mma16816(o[fj], ph[k2], blf);
                mma16816(o[fj], pl[k2], bhf);
            }
        }
    }

    // write normalized output
    float inv0 = 1.0f / lrun[0];
    float inv1 = 1.0f / lrun[1];
    float* orow0 = g_attn + ((size_t)bb * S_ + r0) * D_ + hh * HD_;
    float* orow1 = g_attn + ((size_t)bb * S_ + r1) * D_ + hh * HD_;
    #pragma unroll
    for (int fj = 0; fj < 8; fj++) {
        int cl = fj * 8 + 2 * t;
        float2 w0; w0.x = o[fj][0] * inv0; w0.y = o[fj][1] * inv0;
        float2 w1; w1.x = o[fj][2] * inv1; w1.y = o[fj][3] * inv1;
        *(float2*)&orow0[cl] = w0;
        *(float2*)&orow1[cl] = w1;
    }
}

// ---------------------------------------------------------------------------
extern "C" void kernel_launch(void* const* d_in, const int* in_sizes, int n_in,
                              void* d_out, int out_size)
{
    const float* query = (const float*)d_in[0];
    const float* key_  = (const float*)d_in[1];
    const float* value = (const float*)d_in[2];
    // d_in[3] = mask (tril) — handled analytically as causal
    const float* Wq = (const float*)d_in[4];
    const float* bq = (const float*)d_in[5];
    const float* Wk = (const float*)d_in[6];
    const float* bk = (const float*)d_in[7];
    const float* Wv = (const float*)d_in[8];
    const float* bv = (const float*)d_in[9];
    const float* Wo = (const float*)d_in[10];
    const float* bo = (const float*)d_in[11];
    float* out = (float*)d_out;

    dim3 gproj(D_ / 128, MROWS / 128, 3);       // (6, 64, 3)
    proj_qkv<<<gproj, 256>>>(query, key_, value, Wq, bq, Wk, bk, Wv, bv);

    dim3 gattn(S_ / 64, B_ * H_);               // (64, 24)
    attn_kernel<<<gattn, 128>>>();

    dim3 gout(D_ / 128, MROWS / 128);           // (6, 64)
    proj_out<<<gout, 256>>>(Wo, bo, out);
}

// round 3
// speedup vs baseline: 3.1424x; 1.3823x over previous
#include <cuda_runtime.h>
#include <cuda_bf16.h>
#include <stdint.h>

#define B_  2
#define S_  4096
#define D_  768
#define H_  12
#define HD_ 64
#define MROWS 8192
#define NELEM (B_*H_*S_*HD_)

// ---- pre-split operands (bf16 hi/lo) ----
__device__ __nv_bfloat16 g_xqh[MROWS*D_], g_xql[MROWS*D_];
__device__ __nv_bfloat16 g_xkh[MROWS*D_], g_xkl[MROWS*D_];
__device__ __nv_bfloat16 g_xvh[MROWS*D_], g_xvl[MROWS*D_];
__device__ __nv_bfloat16 g_wqh[D_*D_], g_wql[D_*D_];
__device__ __nv_bfloat16 g_wkh[D_*D_], g_wkl[D_*D_];
__device__ __nv_bfloat16 g_wvh[D_*D_], g_wvl[D_*D_];
__device__ __nv_bfloat16 g_woh[D_*D_], g_wol[D_*D_];
// projected Q/K: [b][h][s][hd]; V transposed: [b][h][hd][s]
__device__ __nv_bfloat16 g_qh[NELEM], g_ql[NELEM];
__device__ __nv_bfloat16 g_kh[NELEM], g_kl[NELEM];
__device__ __nv_bfloat16 g_vth[NELEM], g_vtl[NELEM];
// attention output (split) [b][s][d]
__device__ __nv_bfloat16 g_ah[MROWS*D_], g_al[MROWS*D_];

// ---------------------------------------------------------------------------
// helpers
// ---------------------------------------------------------------------------
__device__ __forceinline__ void split2(float x0, float x1, uint32_t& hi, uint32_t& lo) {
    __nv_bfloat16 h0 = __float2bfloat16(x0);
    __nv_bfloat16 h1 = __float2bfloat16(x1);
    __nv_bfloat16 l0 = __float2bfloat16(x0 - __bfloat162float(h0));
    __nv_bfloat16 l1 = __float2bfloat16(x1 - __bfloat162float(h1));
    hi = ((uint32_t)__bfloat16_as_ushort(h1) << 16) | (uint32_t)__bfloat16_as_ushort(h0);
    lo = ((uint32_t)__bfloat16_as_ushort(l1) << 16) | (uint32_t)__bfloat16_as_ushort(l0);
}

__device__ __forceinline__ void mma16816(float (&c)[4], const uint32_t (&a)[4],
                                         const uint32_t (&b)[2]) {
    asm volatile(
        "mma.sync.aligned.m16n8k16.row.col.f32.bf16.bf16.f32 "
        "{%0,%1,%2,%3}, {%4,%5,%6,%7}, {%8,%9}, {%0,%1,%2,%3};\n"
        : "+f"(c[0]), "+f"(c[1]), "+f"(c[2]), "+f"(c[3])
        : "r"(a[0]), "r"(a[1]), "r"(a[2]), "r"(a[3]), "r"(b[0]), "r"(b[1]));
}

__device__ __forceinline__ uint32_t smem_u32(const void* p) {
    uint32_t a;
    asm("{ .reg .u64 t; cvta.to.shared.u64 t, %1; cvt.u32.u64 %0, t; }" : "=r"(a) : "l"(p));
    return a;
}
__device__ __forceinline__ void cp16(uint32_t d, const void* s) {
    asm volatile("cp.async.ca.shared.global [%0], [%1], 16;" :: "r"(d), "l"(s));
}
__device__ __forceinline__ void cp_commit() { asm volatile("cp.async.commit_group;"); }
template<int N> __device__ __forceinline__ void cp_wait() {
    asm volatile("cp.async.wait_group %0;" :: "n"(N));
}

// ---------------------------------------------------------------------------
// split prep kernels
// ---------------------------------------------------------------------------
__device__ __forceinline__ void split_body(const float* __restrict__ src,
                                           __nv_bfloat16* __restrict__ h,
                                           __nv_bfloat16* __restrict__ l, int n4) {
    for (int i = blockIdx.x * blockDim.x + threadIdx.x; i < n4;
         i += gridDim.x * blockDim.x) {
        float4 v = ((const float4*)src)[i];
        uint32_t h0, l0, h1, l1;
        split2(v.x, v.y, h0, l0);
        split2(v.z, v.w, h1, l1);
        uint2 hw; hw.x = h0; hw.y = h1;
        uint2 lw; lw.x = l0; lw.y = l1;
        ((uint2*)h)[i] = hw;
        ((uint2*)l)[i] = lw;
    }
}

__global__ void split_acts(const float* __restrict__ q, const float* __restrict__ k,
                           const float* __restrict__ v) {
    int z = blockIdx.y;
    const float* src = (z == 0) ? q : (z == 1) ? k : v;
    __nv_bfloat16* h = (z == 0) ? g_xqh : (z == 1) ? g_xkh : g_xvh;
    __nv_bfloat16* l = (z == 0) ? g_xql : (z == 1) ? g_xkl : g_xvl;
    split_body(src, h, l, MROWS * D_ / 4);
}

__global__ void split_wts(const float* __restrict__ wq, const float* __restrict__ wk,
                          const float* __restrict__ wv, const float* __restrict__ wo) {
    int z = blockIdx.y;
    const float* src = (z == 0) ? wq : (z == 1) ? wk : (z == 2) ? wv : wo;
    __nv_bfloat16* h = (z == 0) ? g_wqh : (z == 1) ? g_wkh : (z == 2) ? g_wvh : g_woh;
    __nv_bfloat16* l = (z == 0) ? g_wql : (z == 1) ? g_wkl : (z == 2) ? g_wvl : g_wol;
    split_body(src, h, l, D_ * D_ / 4);
}

// ---------------------------------------------------------------------------
// GEMM core: C = X @ W^T + bias, all operands pre-split bf16 hi/lo.
// 128x128x32 tiles, 256 thr = 8 warps (4m x 2n), warp tile 32x64, bf16x3 MMA.
// cp.async double-buffered smem. emode: 0 = head-split scatter (Q/K),
// 1 = transposed scatter (V), 2 = fp32 row-major out.
// Stage layout (words): Ah[2560] Al[2560] Bh[2560] Bl[2560]; row stride 20 words.
// ---------------------------------------------------------------------------
#define GSTG 10240   // words per stage

__device__ __forceinline__ void gemm_core(
    const __nv_bfloat16* __restrict__ Xh, const __nv_bfloat16* __restrict__ Xl,
    const __nv_bfloat16* __restrict__ Wh, const __nv_bfloat16* __restrict__ Wl,
    const float* __restrict__ bias, float osc, int emode,
    __nv_bfloat16* __restrict__ outh, __nv_bfloat16* __restrict__ outl,
    float* __restrict__ outf)
{
    extern __shared__ uint32_t sm[];
    const uint32_t smb = smem_u32(sm);

    const int tid  = threadIdx.x;
    const int lane = tid & 31;
    const int warp = tid >> 5;
    const int wm = warp >> 1, wn = warp & 1;
    const int g = lane >> 2, t = lane & 3;
    const int m0 = blockIdx.y * 128;
    const int n0 = blockIdx.x * 128;

    // cp.async issue of k-tile kt into stage s
    auto issue = [&](int kt, int s) {
        int k0 = kt * 32;
        #pragma unroll
        for (int p = 0; p < 2; p++) {
            int idx = p * 256 + tid;
            int r = idx >> 2, c8 = (idx & 3) * 8;
            uint32_t dst = smb + (uint32_t)((s * GSTG + r * 20 + (c8 >> 1)) * 4);
            size_t ao = (size_t)(m0 + r) * D_ + k0 + c8;
            size_t bo = (size_t)(n0 + r) * D_ + k0 + c8;
            cp16(dst,            Xh + ao);
            cp16(dst + 2560 * 4, Xl + ao);
            cp16(dst + 5120 * 4, Wh + bo);
            cp16(dst + 7680 * 4, Wl + bo);
        }
        cp_commit();
    };

    float c[2][8][4];
    #pragma unroll
    for (int fi = 0; fi < 2; fi++)
        #pragma unroll
        for (int fj = 0; fj < 8; fj++)
            #pragma unroll
            for (int e = 0; e < 4; e++) c[fi][fj][e] = 0.0f;

    issue(0, 0);

    for (int kt = 0; kt < 24; kt++) {
        if (kt < 23) { issue(kt + 1, (kt + 1) & 1); cp_wait<1>(); }
        else         { cp_wait<0>(); }
        __syncthreads();

        const uint32_t* Ah = sm + (kt & 1) * GSTG;
        const uint32_t* Al = Ah + 2560;
        const uint32_t* Bh = Ah + 5120;
        const uint32_t* Bl = Ah + 7680;

        #pragma unroll
        for (int ks = 0; ks < 2; ks++) {
            uint32_t ah[2][4], al[2][4];
            #pragma unroll
            for (int fi = 0; fi < 2; fi++) {
                int base = (wm * 32 + fi * 16 + g) * 20 + ks * 8 + t;
                ah[fi][0] = Ah[base];
                ah[fi][1] = Ah[base + 8 * 20];
                ah[fi][2] = Ah[base + 4];
                ah[fi][3] = Ah[base + 8 * 20 + 4];
                al[fi][0] = Al[base];
                al[fi][1] = Al[base + 8 * 20];
                al[fi][2] = Al[base + 4];
                al[fi][3] = Al[base + 8 * 20 + 4];
            }
            #pragma unroll
            for (int fj = 0; fj < 8; fj++) {
                int bw = (wn * 64 + fj * 8 + g) * 20 + ks * 8 + t;
                uint32_t bhf[2] = { Bh[bw], Bh[bw + 4] };
                uint32_t blf[2] = { Bl[bw], Bl[bw + 4] };
                #pragma unroll
                for (int fi = 0; fi < 2; fi++) {
                    mma16816(c[fi][fj], ah[fi], bhf);
                    mma16816(c[fi][fj], ah[fi], blf);
                    mma16816(c[fi][fj], al[fi], bhf);
                }
            }
        }
        __syncthreads();
    }

    // epilogue
    #pragma unroll
    for (int fi = 0; fi < 2; fi++) {
        #pragma unroll
        for (int rr = 0; rr < 2; rr++) {
            int m = m0 + wm * 32 + fi * 16 + g + rr * 8;
            #pragma unroll
            for (int fj = 0; fj < 8; fj++) {
                int n = n0 + wn * 64 + fj * 8 + 2 * t;
                float v0 = c[fi][fj][rr * 2 + 0] + bias[n];
                float v1 = c[fi][fj][rr * 2 + 1] + bias[n + 1];
                if (emode == 0) {
                    v0 *= osc; v1 *= osc;
                    int bb = m >> 12, ss = m & 4095;
                    int hh = n >> 6,  hd = n & 63;
                    size_t off = (((size_t)bb * H_ + hh) * S_ + ss) * HD_ + hd;
                    uint32_t hw, lw;
                    split2(v0, v1, hw, lw);
                    *(uint32_t*)&outh[off] = hw;
                    *(uint32_t*)&outl[off] = lw;
                } else if (emode == 1) {
                    // V transposed scatter: [b][h][hd][s]
                    int bb = m >> 12, ss = m & 4095;
                    int hh = n >> 6,  hd = n & 63;
                    size_t base = (((size_t)bb * H_ + hh) * HD_ + hd) * S_ + ss;
                    __nv_bfloat16 h0 = __float2bfloat16(v0);
                    __nv_bfloat16 l0 = __float2bfloat16(v0 - __bfloat162float(h0));
                    __nv_bfloat16 h1 = __float2bfloat16(v1);
                    __nv_bfloat16 l1 = __float2bfloat16(v1 - __bfloat162float(h1));
                    outh[base] = h0;       outl[base] = l0;
                    outh[base + S_] = h1;  outl[base + S_] = l1;
                } else {
                    float2 o2; o2.x = v0; o2.y = v1;
                    *(float2*)&outf[(size_t)m * D_ + n] = o2;
                }
            }
        }
    }
}

__global__ void __launch_bounds__(256, 2) proj_qkv(
    const float* __restrict__ bq, const float* __restrict__ bk, const float* __restrict__ bv)
{
    int z = blockIdx.z;
    const __nv_bfloat16* Xh = (z == 0) ? g_xqh : (z == 1) ? g_xkh : g_xvh;
    const __nv_bfloat16* Xl = (z == 0) ? g_xql : (z == 1) ? g_xkl : g_xvl;
    const __nv_bfloat16* Wh = (z == 0) ? g_wqh : (z == 1) ? g_wkh : g_wvh;
    const __nv_bfloat16* Wl = (z == 0) ? g_wql : (z == 1) ? g_wkl : g_wvl;
    const float* bias = (z == 0) ? bq : (z == 1) ? bk : bv;
    __nv_bfloat16* oh = (z == 0) ? g_qh : (z == 1) ? g_kh : g_vth;
    __nv_bfloat16* ol = (z == 0) ? g_ql : (z == 1) ? g_kl : g_vtl;
    float osc = (z == 0) ? 0.125f : 1.0f;
    gemm_core(Xh, Xl, Wh, Wl, bias, osc, (z == 2) ? 1 : 0, oh, ol, nullptr);
}

__global__ void __launch_bounds__(256, 2) proj_out(
    const float* __restrict__ bo, float* __restrict__ out)
{
    gemm_core(g_ah, g_al, g_woh, g_wol, bo, 1.0f, 2, nullptr, nullptr, out);
}

// ---------------------------------------------------------------------------
// Flash attention, causal, bf16x3 MMA. 64 q-rows/CTA, 64-key tiles,
// 128 thr = 4 warps x 16 rows. cp.async double-buffered K/V tiles.
// Stage layout (words): Kh[2304] Kl[2304] Vh[2304] Vl[2304]; row stride 36 words.
// K rows = key (hd cols); V rows = hd (seq cols, pre-transposed in proj).
// ---------------------------------------------------------------------------
#define ASTG 9216   // words per stage

__global__ void __launch_bounds__(128, 3) attn_kernel()
{
    extern __shared__ uint32_t sm[];
    const uint32_t smb = smem_u32(sm);

    const int tid  = threadIdx.x;
    const int lane = tid & 31;
    const int wm   = tid >> 5;
    const int g    = lane >> 2;
    const int t    = lane & 3;
    const int qt = gridDim.x - 1 - blockIdx.x;   // heavy CTAs first
    const int bh = blockIdx.y;
    const int bb = bh / H_;
    const int hh = bh % H_;
    const int q0 = qt * 64;

    auto issue = [&](int jt, int s) {
        int k0 = jt * 64;
        #pragma unroll
        for (int p = 0; p < 4; p++) {
            int idx = p * 128 + tid;
            int row = idx >> 3, c8 = (idx & 7) * 8;
            uint32_t dst = smb + (uint32_t)((s * ASTG + row * 36 + (c8 >> 1)) * 4);
            size_t ko = ((size_t)bh * S_ + k0 + row) * HD_ + c8;
            size_t vo = ((size_t)bh * HD_ + row) * S_ + k0 + c8;
            cp16(dst,            g_kh + ko);
            cp16(dst + 2304 * 4, g_kl + ko);
            cp16(dst + 4608 * 4, g_vth + vo);
            cp16(dst + 6912 * 4, g_vtl + vo);
        }
        cp_commit();
    };

    issue(0, 0);

    // Q fragments in registers
    uint32_t qh[4][4], ql[4][4];
    {
        const __nv_bfloat16* qb  = g_qh + ((size_t)bh * S_ + q0 + wm * 16) * HD_;
        const __nv_bfloat16* qlb = g_ql + ((size_t)bh * S_ + q0 + wm * 16) * HD_;
        #pragma unroll
        for (int kt = 0; kt < 4; kt++) {
            int kc = kt * 16 + 2 * t;
            qh[kt][0] = *(const uint32_t*)&qb[(size_t)g * HD_ + kc];
            qh[kt][1] = *(const uint32_t*)&qb[(size_t)(g + 8) * HD_ + kc];
            qh[kt][2] = *(const uint32_t*)&qb[(size_t)g * HD_ + kc + 8];
            qh[kt][3] = *(const uint32_t*)&qb[(size_t)(g + 8) * HD_ + kc + 8];
            ql[kt][0] = *(const uint32_t*)&qlb[(size_t)g * HD_ + kc];
            ql[kt][1] = *(const uint32_t*)&qlb[(size_t)(g + 8) * HD_ + kc];
            ql[kt][2] = *(const uint32_t*)&qlb[(size_t)g * HD_ + kc + 8];
            ql[kt][3] = *(const uint32_t*)&qlb[(size_t)(g + 8) * HD_ + kc + 8];
        }
    }

    float o[8][4];
    float mrun[2], lrun[2];
    mrun[0] = mrun[1] = -1e30f;
    lrun[0] = lrun[1] = 0.0f;
    #pragma unroll
    for (int fj = 0; fj < 8; fj++)
        #pragma unroll
        for (int e = 0; e < 4; e++) o[fj][e] = 0.0f;

    const int r0 = q0 + wm * 16 + g;
    const int r1 = r0 + 8;

    for (int jt = 0; jt <= qt; jt++) {
        const int k0 = jt * 64;
        if (jt < qt) { issue(jt + 1, (jt + 1) & 1); cp_wait<1>(); }
        else         { cp_wait<0>(); }
        __syncthreads();

        const uint32_t* Khw = sm + (jt & 1) * ASTG;
        const uint32_t* Klw = Khw + 2304;
        const uint32_t* Vhw = Khw + 4608;
        const uint32_t* Vlw = Khw + 6912;

        // S = Q @ K^T
        float s[8][4];
        #pragma unroll
        for (int fj = 0; fj < 8; fj++)
            #pragma unroll
            for (int e = 0; e < 4; e++) s[fj][e] = 0.0f;

        #pragma unroll
        for (int kt = 0; kt < 4; kt++) {
            #pragma unroll
            for (int fj = 0; fj < 8; fj++) {
                int bw = (fj * 8 + g) * 36 + kt * 8 + t;
                uint32_t bhf[2] = { Khw[bw], Khw[bw + 4] };
                uint32_t blf[2] = { Klw[bw], Klw[bw + 4] };
                mma16816(s[fj], qh[kt], bhf);
                mma16816(s[fj], qh[kt], blf);
                mma16816(s[fj], ql[kt], bhf);
            }
        }

        if (jt == qt) {
            #pragma unroll
            for (int fj = 0; fj < 8; fj++) {
                int cn = k0 + fj * 8 + 2 * t;
                if (cn     > r0) s[fj][0] = -1e30f;
                if (cn + 1 > r0) s[fj][1] = -1e30f;
                if (cn     > r1) s[fj][2] = -1e30f;
                if (cn + 1 > r1) s[fj][3] = -1e30f;
            }
        }

        // online softmax
        #pragma unroll
        for (int r = 0; r < 2; r++) {
            float mx = -1e30f;
            #pragma unroll
            for (int fj = 0; fj < 8; fj++)
                mx = fmaxf(mx, fmaxf(s[fj][2 * r], s[fj][2 * r + 1]));
            mx = fmaxf(mx, __shfl_xor_sync(0xffffffffu, mx, 1));
            mx = fmaxf(mx, __shfl_xor_sync(0xffffffffu, mx, 2));
            float mnew  = fmaxf(mrun[r], mx);
            float scale = __expf(mrun[r] - mnew);
            float sum = 0.0f;
            #pragma unroll
            for (int fj = 0; fj < 8; fj++) {
                float p0 = __expf(s[fj][2 * r]     - mnew);
                float p1 = __expf(s[fj][2 * r + 1] - mnew);
                s[fj][2 * r] = p0; s[fj][2 * r + 1] = p1;
                sum += p0 + p1;
            }
            sum += __shfl_xor_sync(0xffffffffu, sum, 1);
            sum += __shfl_xor_sync(0xffffffffu, sum, 2);
            lrun[r] = lrun[r] * scale + sum;
            mrun[r] = mnew;
            #pragma unroll
            for (int fj = 0; fj < 8; fj++) {
                o[fj][2 * r]     *= scale;
                o[fj][2 * r + 1] *= scale;
            }
        }

        // pack P into A-fragments
        uint32_t ph[4][4], pl[4][4];
        #pragma unroll
        for (int k2 = 0; k2 < 4; k2++) {
            split2(s[2 * k2][0],     s[2 * k2][1],     ph[k2][0], pl[k2][0]);
            split2(s[2 * k2][2],     s[2 * k2][3],     ph[k2][1], pl[k2][1]);
            split2(s[2 * k2 + 1][0], s[2 * k2 + 1][1], ph[k2][2], pl[k2][2]);
            split2(s[2 * k2 + 1][2], s[2 * k2 + 1][3], ph[k2][3], pl[k2][3]);
        }

        // O += P @ V
        #pragma unroll
        for (int k2 = 0; k2 < 4; k2++) {
            #pragma unroll
            for (int fj = 0; fj < 8; fj++) {
                int bw = (fj * 8 + g) * 36 + k2 * 8 + t;
                uint32_t bhf[2] = { Vhw[bw], Vhw[bw + 4] };
                uint32_t blf[2] = { Vlw[bw], Vlw[bw + 4] };
                mma16816(o[fj], ph[k2], bhf);
                mma16816(o[fj], ph[k2], blf);
                mma16816(o[fj], pl[k2], bhf);
            }
        }
        __syncthreads();
    }

    // write normalized output (split hi/lo for out-proj)
    float inv0 = 1.0f / lrun[0];
    float inv1 = 1.0f / lrun[1];
    size_t off0 = ((size_t)bb * S_ + r0) * D_ + hh * HD_;
    size_t off1 = ((size_t)bb * S_ + r1) * D_ + hh * HD_;
    #pragma unroll
    for (int fj = 0; fj < 8; fj++) {
        int cl = fj * 8 + 2 * t;
        uint32_t hw, lw;
        split2(o[fj][0] * inv0, o[fj][1] * inv0, hw, lw);
        *(uint32_t*)&g_ah[off0 + cl] = hw;
        *(uint32_t*)&g_al[off0 + cl] = lw;
        split2(o[fj][2] * inv1, o[fj][3] * inv1, hw, lw);
        *(uint32_t*)&g_ah[off1 + cl] = hw;
        *(uint32_t*)&g_al[off1 + cl] = lw;
    }
}

// ---------------------------------------------------------------------------
extern "C" void kernel_launch(void* const* d_in, const int* in_sizes, int n_in,
                              void* d_out, int out_size)
{
    const float* query = (const float*)d_in[0];
    const float* key_  = (const float*)d_in[1];
    const float* value = (const float*)d_in[2];
    // d_in[3] = mask (tril) — handled analytically as causal
    const float* Wq = (const float*)d_in[4];
    const float* bq = (const float*)d_in[5];
    const float* Wk = (const float*)d_in[6];
    const float* bk = (const float*)d_in[7];
    const float* Wv = (const float*)d_in[8];
    const float* bv = (const float*)d_in[9];
    const float* Wo = (const float*)d_in[10];
    const float* bo = (const float*)d_in[11];
    float* out = (float*)d_out;

    cudaFuncSetAttribute(proj_qkv,   cudaFuncAttributeMaxDynamicSharedMemorySize, 2 * GSTG * 4);
    cudaFuncSetAttribute(proj_out,   cudaFuncAttributeMaxDynamicSharedMemorySize, 2 * GSTG * 4);
    cudaFuncSetAttribute(attn_kernel,cudaFuncAttributeMaxDynamicSharedMemorySize, 2 * ASTG * 4);

    split_acts<<<dim3(512, 3), 256>>>(query, key_, value);
    split_wts<<<dim3(64, 4), 256>>>(Wq, Wk, Wv, Wo);

    dim3 gproj(D_ / 128, MROWS / 128, 3);
    proj_qkv<<<gproj, 256, 2 * GSTG * 4>>>(bq, bk, bv);

    dim3 gattn(S_ / 64, B_ * H_);
    attn_kernel<<<gattn, 128, 2 * ASTG * 4>>>();

    dim3 gout(D_ / 128, MROWS / 128);
    proj_out<<<gout, 256, 2 * GSTG * 4>>>(bo, out);
}

// round 4
// speedup vs baseline: 3.9169x; 1.2465x over previous
#include <cuda_runtime.h>
#include <cuda_bf16.h>
#include <cuda_fp16.h>
#include <stdint.h>

#define B_  2
#define S_  4096
#define D_  768
#define H_  12
#define HD_ 64
#define MROWS 8192
#define NELEM (B_*H_*S_*HD_)

// ---- pre-split inputs for projections (bf16 hi/lo, bf16x3 GEMM) ----
__device__ __nv_bfloat16 g_xqh[MROWS*D_], g_xql[MROWS*D_];
__device__ __nv_bfloat16 g_xkh[MROWS*D_], g_xkl[MROWS*D_];
__device__ __nv_bfloat16 g_xvh[MROWS*D_], g_xvl[MROWS*D_];
__device__ __nv_bfloat16 g_wqh[D_*D_], g_wql[D_*D_];
__device__ __nv_bfloat16 g_wkh[D_*D_], g_wkl[D_*D_];
__device__ __nv_bfloat16 g_wvh[D_*D_], g_wvl[D_*D_];
__device__ __nv_bfloat16 g_woh[D_*D_], g_wol[D_*D_];
// projected Q (fp16 hi/lo), K (fp16 single): [b][h][s][hd]; V (fp16 hi/lo) transposed [b][h][hd][s]
__device__ __half g_qh[NELEM], g_ql[NELEM];
__device__ __half g_kh[NELEM];
__device__ __half g_vth[NELEM], g_vtl[NELEM];
// attention output (bf16 hi/lo) [b][s][d]
__device__ __nv_bfloat16 g_ah[MROWS*D_], g_al[MROWS*D_];

// ---------------------------------------------------------------------------
// helpers
// ---------------------------------------------------------------------------
__device__ __forceinline__ void split2(float x0, float x1, uint32_t& hi, uint32_t& lo) {
    __nv_bfloat16 h0 = __float2bfloat16(x0);
    __nv_bfloat16 h1 = __float2bfloat16(x1);
    __nv_bfloat16 l0 = __float2bfloat16(x0 - __bfloat162float(h0));
    __nv_bfloat16 l1 = __float2bfloat16(x1 - __bfloat162float(h1));
    hi = ((uint32_t)__bfloat16_as_ushort(h1) << 16) | (uint32_t)__bfloat16_as_ushort(h0);
    lo = ((uint32_t)__bfloat16_as_ushort(l1) << 16) | (uint32_t)__bfloat16_as_ushort(l0);
}

// pack two floats into f16x2 (x0 -> low half, x1 -> high half)
__device__ __forceinline__ uint32_t pack_h2(float x0, float x1) {
    uint32_t r;
    asm("cvt.rn.f16x2.f32 %0, %1, %2;" : "=r"(r) : "f"(x1), "f"(x0));
    return r;
}
// fp16 hi/lo split of a float pair
__device__ __forceinline__ void split2h(float x0, float x1, uint32_t& hi, uint32_t& lo) {
    __half h0 = __float2half_rn(x0);
    __half h1 = __float2half_rn(x1);
    hi = ((uint32_t)__half_as_ushort(h1) << 16) | (uint32_t)__half_as_ushort(h0);
    lo = pack_h2(x0 - __half2float(h0), x1 - __half2float(h1));
}

__device__ __forceinline__ void mma16816(float (&c)[4], const uint32_t (&a)[4],
                                         const uint32_t (&b)[2]) {
    asm volatile(
        "mma.sync.aligned.m16n8k16.row.col.f32.bf16.bf16.f32 "
        "{%0,%1,%2,%3}, {%4,%5,%6,%7}, {%8,%9}, {%0,%1,%2,%3};\n"
        : "+f"(c[0]), "+f"(c[1]), "+f"(c[2]), "+f"(c[3])
        : "r"(a[0]), "r"(a[1]), "r"(a[2]), "r"(a[3]), "r"(b[0]), "r"(b[1]));
}
__device__ __forceinline__ void mma16816h(float (&c)[4], const uint32_t (&a)[4],
                                          const uint32_t (&b)[2]) {
    asm volatile(
        "mma.sync.aligned.m16n8k16.row.col.f32.f16.f16.f32 "
        "{%0,%1,%2,%3}, {%4,%5,%6,%7}, {%8,%9}, {%0,%1,%2,%3};\n"
        : "+f"(c[0]), "+f"(c[1]), "+f"(c[2]), "+f"(c[3])
        : "r"(a[0]), "r"(a[1]), "r"(a[2]), "r"(a[3]), "r"(b[0]), "r"(b[1]));
}

__device__ __forceinline__ uint32_t smem_u32(const void* p) {
    uint32_t a;
    asm("{ .reg .u64 t; cvta.to.shared.u64 t, %1; cvt.u32.u64 %0, t; }" : "=r"(a) : "l"(p));
    return a;
}
__device__ __forceinline__ void cp16(uint32_t d, const void* s) {
    asm volatile("cp.async.ca.shared.global [%0], [%1], 16;" :: "r"(d), "l"(s));
}
__device__ __forceinline__ void cp_commit() { asm volatile("cp.async.commit_group;"); }
template<int N> __device__ __forceinline__ void cp_wait() {
    asm volatile("cp.async.wait_group %0;" :: "n"(N));
}

// ---------------------------------------------------------------------------
// split prep kernels
// ---------------------------------------------------------------------------
__device__ __forceinline__ void split_body(const float* __restrict__ src,
                                           __nv_bfloat16* __restrict__ h,
                                           __nv_bfloat16* __restrict__ l, int n4) {
    for (int i = blockIdx.x * blockDim.x + threadIdx.x; i < n4;
         i += gridDim.x * blockDim.x) {
        float4 v = ((const float4*)src)[i];
        uint32_t h0, l0, h1, l1;
        split2(v.x, v.y, h0, l0);
        split2(v.z, v.w, h1, l1);
        uint2 hw; hw.x = h0; hw.y = h1;
        uint2 lw; lw.x = l0; lw.y = l1;
        ((uint2*)h)[i] = hw;
        ((uint2*)l)[i] = lw;
    }
}

__global__ void split_acts(const float* __restrict__ q, const float* __restrict__ k,
                           const float* __restrict__ v) {
    int z = blockIdx.y;
    const float* src = (z == 0) ? q : (z == 1) ? k : v;
    __nv_bfloat16* h = (z == 0) ? g_xqh : (z == 1) ? g_xkh : g_xvh;
    __nv_bfloat16* l = (z == 0) ? g_xql : (z == 1) ? g_xkl : g_xvl;
    split_body(src, h, l, MROWS * D_ / 4);
}

__global__ void split_wts(const float* __restrict__ wq, const float* __restrict__ wk,
                          const float* __restrict__ wv, const float* __restrict__ wo) {
    int z = blockIdx.y;
    const float* src = (z == 0) ? wq : (z == 1) ? wk : (z == 2) ? wv : wo;
    __nv_bfloat16* h = (z == 0) ? g_wqh : (z == 1) ? g_wkh : (z == 2) ? g_wvh : g_woh;
    __nv_bfloat16* l = (z == 0) ? g_wql : (z == 1) ? g_wkl : (z == 2) ? g_wvl : g_wol;
    split_body(src, h, l, D_ * D_ / 4);
}

// ---------------------------------------------------------------------------
// GEMM core (bf16x3): C = X @ W^T + bias. 128x128x32 tiles, 256 thr, cp.async
// double-buffered. emode: 0=Q fp16 hi/lo head-split, 1=K fp16 single head-split,
// 2=V fp16 hi/lo transposed, 3=fp32 row-major out.
// ---------------------------------------------------------------------------
#define GSTG 10240   // words per stage

__device__ __forceinline__ void gemm_core(
    const __nv_bfloat16* __restrict__ Xh, const __nv_bfloat16* __restrict__ Xl,
    const __nv_bfloat16* __restrict__ Wh, const __nv_bfloat16* __restrict__ Wl,
    const float* __restrict__ bias, float osc, int emode,
    __half* __restrict__ outh, __half* __restrict__ outl,
    float* __restrict__ outf)
{
    extern __shared__ uint32_t sm[];
    const uint32_t smb = smem_u32(sm);

    const int tid  = threadIdx.x;
    const int lane = tid & 31;
    const int warp = tid >> 5;
    const int wm = warp >> 1, wn = warp & 1;
    const int g = lane >> 2, t = lane & 3;
    const int m0 = blockIdx.y * 128;
    const int n0 = blockIdx.x * 128;

    auto issue = [&](int kt, int s) {
        int k0 = kt * 32;
        #pragma unroll
        for (int p = 0; p < 2; p++) {
            int idx = p * 256 + tid;
            int r = idx >> 2, c8 = (idx & 3) * 8;
            uint32_t dst = smb + (uint32_t)((s * GSTG + r * 20 + (c8 >> 1)) * 4);
            size_t ao = (size_t)(m0 + r) * D_ + k0 + c8;
            size_t bo = (size_t)(n0 + r) * D_ + k0 + c8;
            cp16(dst,            Xh + ao);
            cp16(dst + 2560 * 4, Xl + ao);
            cp16(dst + 5120 * 4, Wh + bo);
            cp16(dst + 7680 * 4, Wl + bo);
        }
        cp_commit();
    };

    float c[2][8][4];
    #pragma unroll
    for (int fi = 0; fi < 2; fi++)
        #pragma unroll
        for (int fj = 0; fj < 8; fj++)
            #pragma unroll
            for (int e = 0; e < 4; e++) c[fi][fj][e] = 0.0f;

    issue(0, 0);

    for (int kt = 0; kt < 24; kt++) {
        if (kt < 23) { issue(kt + 1, (kt + 1) & 1); cp_wait<1>(); }
        else         { cp_wait<0>(); }
        __syncthreads();

        const uint32_t* Ah = sm + (kt & 1) * GSTG;
        const uint32_t* Al = Ah + 2560;
        const uint32_t* Bh = Ah + 5120;
        const uint32_t* Bl = Ah + 7680;

        #pragma unroll
        for (int ks = 0; ks < 2; ks++) {
            uint32_t ah[2][4], al[2][4];
            #pragma unroll
            for (int fi = 0; fi < 2; fi++) {
                int base = (wm * 32 + fi * 16 + g) * 20 + ks * 8 + t;
                ah[fi][0] = Ah[base];
                ah[fi][1] = Ah[base + 8 * 20];
                ah[fi][2] = Ah[base + 4];
                ah[fi][3] = Ah[base + 8 * 20 + 4];
                al[fi][0] = Al[base];
                al[fi][1] = Al[base + 8 * 20];
                al[fi][2] = Al[base + 4];
                al[fi][3] = Al[base + 8 * 20 + 4];
            }
            #pragma unroll
            for (int fj = 0; fj < 8; fj++) {
                int bw = (wn * 64 + fj * 8 + g) * 20 + ks * 8 + t;
                uint32_t bhf[2] = { Bh[bw], Bh[bw + 4] };
                uint32_t blf[2] = { Bl[bw], Bl[bw + 4] };
                #pragma unroll
                for (int fi = 0; fi < 2; fi++) {
                    mma16816(c[fi][fj], ah[fi], bhf);
                    mma16816(c[fi][fj], ah[fi], blf);
                    mma16816(c[fi][fj], al[fi], bhf);
                }
            }
        }
        __syncthreads();
    }

    // epilogue
    #pragma unroll
    for (int fi = 0; fi < 2; fi++) {
        #pragma unroll
        for (int rr = 0; rr < 2; rr++) {
            int m = m0 + wm * 32 + fi * 16 + g + rr * 8;
            #pragma unroll
            for (int fj = 0; fj < 8; fj++) {
                int n = n0 + wn * 64 + fj * 8 + 2 * t;
                float v0 = c[fi][fj][rr * 2 + 0] + bias[n];
                float v1 = c[fi][fj][rr * 2 + 1] + bias[n + 1];
                if (emode <= 1) {
                    v0 *= osc; v1 *= osc;
                    int bb = m >> 12, ss = m & 4095;
                    int hh = n >> 6,  hd = n & 63;
                    size_t off = (((size_t)bb * H_ + hh) * S_ + ss) * HD_ + hd;
                    if (emode == 0) {
                        uint32_t hw, lw;
                        split2h(v0, v1, hw, lw);
                        *(uint32_t*)&outh[off] = hw;
                        *(uint32_t*)&outl[off] = lw;
                    } else {
                        *(uint32_t*)&outh[off] = pack_h2(v0, v1);
                    }
                } else if (emode == 2) {
                    int bb = m >> 12, ss = m & 4095;
                    int hh = n >> 6,  hd = n & 63;
                    size_t base = (((size_t)bb * H_ + hh) * HD_ + hd) * S_ + ss;
                    __half h0 = __float2half_rn(v0);
                    __half h1 = __float2half_rn(v1);
                    outh[base]      = h0;
                    outl[base]      = __float2half_rn(v0 - __half2float(h0));
                    outh[base + S_] = h1;
                    outl[base + S_] = __float2half_rn(v1 - __half2float(h1));
                } else {
                    float2 o2; o2.x = v0; o2.y = v1;
                    *(float2*)&outf[(size_t)m * D_ + n] = o2;
                }
            }
        }
    }
}

__global__ void __launch_bounds__(256, 2) proj_qkv(
    const float* __restrict__ bq, const float* __restrict__ bk, const float* __restrict__ bv)
{
    int z = blockIdx.z;
    const __nv_bfloat16* Xh = (z == 0) ? g_xqh : (z == 1) ? g_xkh : g_xvh;
    const __nv_bfloat16* Xl = (z == 0) ? g_xql : (z == 1) ? g_xkl : g_xvl;
    const __nv_bfloat16* Wh = (z == 0) ? g_wqh : (z == 1) ? g_wkh : g_wvh;
    const __nv_bfloat16* Wl = (z == 0) ? g_wql : (z == 1) ? g_wkl : g_wvl;
    const float* bias = (z == 0) ? bq : (z == 1) ? bk : bv;
    __half* oh = (z == 0) ? g_qh : (z == 1) ? g_kh : g_vth;
    __half* ol = (z == 0) ? g_ql : (z == 1) ? nullptr : g_vtl;
    float osc = (z == 0) ? 0.125f : 1.0f;
    gemm_core(Xh, Xl, Wh, Wl, bias, osc, z, oh, ol, nullptr);
}

// out-proj consumes bf16 hi/lo attention output
__device__ __forceinline__ void gemm_core_bf(
    const __nv_bfloat16* Xh, const __nv_bfloat16* Xl,
    const __nv_bfloat16* Wh, const __nv_bfloat16* Wl,
    const float* bias, float* outf)
{
    gemm_core(Xh, Xl, Wh, Wl, bias, 1.0f, 3, nullptr, nullptr, outf);
}

__global__ void __launch_bounds__(256, 2) proj_out(
    const float* __restrict__ bo, float* __restrict__ out)
{
    gemm_core_bf(g_ah, g_al, g_woh, g_wol, bo, out);
}

// ---------------------------------------------------------------------------
// Flash attention, causal, fp16 MMA (Q hi/lo x K single; P single x V hi/lo).
// 64 q-rows/CTA, 64-key tiles, 128 thr = 4 warps x 16 rows.
// Stage (words): Kh[2304] Vh[2304] Vl[2304]; row stride 36 words (72 halves).
// K rows = key (hd cols); V rows = hd (seq cols, pre-transposed).
// ---------------------------------------------------------------------------
#define ASTG 6912   // words per stage

__global__ void __launch_bounds__(128, 3) attn_kernel()
{
    extern __shared__ uint32_t sm[];
    const uint32_t smb = smem_u32(sm);

    const int tid  = threadIdx.x;
    const int lane = tid & 31;
    const int wm   = tid >> 5;
    const int g    = lane >> 2;
    const int t    = lane & 3;
    const int qt = gridDim.x - 1 - blockIdx.x;   // heavy CTAs first
    const int bh = blockIdx.y;
    const int bb = bh / H_;
    const int hh = bh % H_;
    const int q0 = qt * 64;

    auto issue = [&](int jt, int s) {
        int k0 = jt * 64;
        #pragma unroll
        for (int p = 0; p < 4; p++) {
            int idx = p * 128 + tid;
            int row = idx >> 3, c8 = (idx & 7) * 8;
            uint32_t dst = smb + (uint32_t)((s * ASTG + row * 36 + (c8 >> 1)) * 4);
            size_t ko = ((size_t)bh * S_ + k0 + row) * HD_ + c8;
            size_t vo = ((size_t)bh * HD_ + row) * S_ + k0 + c8;
            cp16(dst,            g_kh  + ko);
            cp16(dst + 2304 * 4, g_vth + vo);
            cp16(dst + 4608 * 4, g_vtl + vo);
        }
        cp_commit();
    };

    issue(0, 0);

    // Q fragments (fp16 hi/lo) in registers
    uint32_t qh[4][4], ql[4][4];
    {
        const __half* qb  = g_qh + ((size_t)bh * S_ + q0 + wm * 16) * HD_;
        const __half* qlb = g_ql + ((size_t)bh * S_ + q0 + wm * 16) * HD_;
        #pragma unroll
        for (int kt = 0; kt < 4; kt++) {
            int kc = kt * 16 + 2 * t;
            qh[kt][0] = *(const uint32_t*)&qb[(size_t)g * HD_ + kc];
            qh[kt][1] = *(const uint32_t*)&qb[(size_t)(g + 8) * HD_ + kc];
            qh[kt][2] = *(const uint32_t*)&qb[(size_t)g * HD_ + kc + 8];
            qh[kt][3] = *(const uint32_t*)&qb[(size_t)(g + 8) * HD_ + kc + 8];
            ql[kt][0] = *(const uint32_t*)&qlb[(size_t)g * HD_ + kc];
            ql[kt][1] = *(const uint32_t*)&qlb[(size_t)(g + 8) * HD_ + kc];
            ql[kt][2] = *(const uint32_t*)&qlb[(size_t)g * HD_ + kc + 8];
            ql[kt][3] = *(const uint32_t*)&qlb[(size_t)(g + 8) * HD_ + kc + 8];
        }
    }

    float o[8][4];
    float mrun[2], lrun[2];
    mrun[0] = mrun[1] = -1e30f;
    lrun[0] = lrun[1] = 0.0f;
    #pragma unroll
    for (int fj = 0; fj < 8; fj++)
        #pragma unroll
        for (int e = 0; e < 4; e++) o[fj][e] = 0.0f;

    const int r0 = q0 + wm * 16 + g;
    const int r1 = r0 + 8;

    for (int jt = 0; jt <= qt; jt++) {
        const int k0 = jt * 64;
        if (jt < qt) { issue(jt + 1, (jt + 1) & 1); cp_wait<1>(); }
        else         { cp_wait<0>(); }
        __syncthreads();

        const uint32_t* Khw = sm + (jt & 1) * ASTG;
        const uint32_t* Vhw = Khw + 2304;
        const uint32_t* Vlw = Khw + 4608;

        // S = Q @ K^T (2 fp16 MMAs: qh.kh + ql.kh)
        float s[8][4];
        #pragma unroll
        for (int fj = 0; fj < 8; fj++)
            #pragma unroll
            for (int e = 0; e < 4; e++) s[fj][e] = 0.0f;

        #pragma unroll
        for (int kt = 0; kt < 4; kt++) {
            #pragma unroll
            for (int fj = 0; fj < 8; fj++) {
                int bw = (fj * 8 + g) * 36 + kt * 8 + t;
                uint32_t kf[2] = { Khw[bw], Khw[bw + 4] };
                mma16816h(s[fj], qh[kt], kf);
                mma16816h(s[fj], ql[kt], kf);
            }
        }

        if (jt == qt) {
            #pragma unroll
            for (int fj = 0; fj < 8; fj++) {
                int cn = k0 + fj * 8 + 2 * t;
                if (cn     > r0) s[fj][0] = -1e30f;
                if (cn + 1 > r0) s[fj][1] = -1e30f;
                if (cn     > r1) s[fj][2] = -1e30f;
                if (cn + 1 > r1) s[fj][3] = -1e30f;
            }
        }

        // online softmax
        #pragma unroll
        for (int r = 0; r < 2; r++) {
            float mx = -1e30f;
            #pragma unroll
            for (int fj = 0; fj < 8; fj++)
                mx = fmaxf(mx, fmaxf(s[fj][2 * r], s[fj][2 * r + 1]));
            mx = fmaxf(mx, __shfl_xor_sync(0xffffffffu, mx, 1));
            mx = fmaxf(mx, __shfl_xor_sync(0xffffffffu, mx, 2));
            float mnew  = fmaxf(mrun[r], mx);
            float scale = __expf(mrun[r] - mnew);
            float sum = 0.0f;
            #pragma unroll
            for (int fj = 0; fj < 8; fj++) {
                float p0 = __expf(s[fj][2 * r]     - mnew);
                float p1 = __expf(s[fj][2 * r + 1] - mnew);
                s[fj][2 * r] = p0; s[fj][2 * r + 1] = p1;
                sum += p0 + p1;
            }
            sum += __shfl_xor_sync(0xffffffffu, sum, 1);
            sum += __shfl_xor_sync(0xffffffffu, sum, 2);
            lrun[r] = lrun[r] * scale + sum;
            mrun[r] = mnew;
            #pragma unroll
            for (int fj = 0; fj < 8; fj++) {
                o[fj][2 * r]     *= scale;
                o[fj][2 * r + 1] *= scale;
            }
        }

        // pack P into fp16 A-fragments (single precision)
        uint32_t ph[4][4];
        #pragma unroll
        for (int k2 = 0; k2 < 4; k2++) {
            ph[k2][0] = pack_h2(s[2 * k2][0],     s[2 * k2][1]);
            ph[k2][1] = pack_h2(s[2 * k2][2],     s[2 * k2][3]);
            ph[k2][2] = pack_h2(s[2 * k2 + 1][0], s[2 * k2 + 1][1]);
            ph[k2][3] = pack_h2(s[2 * k2 + 1][2], s[2 * k2 + 1][3]);
        }

        // O += P @ V (2 fp16 MMAs: ph.vh + ph.vl)
        #pragma unroll
        for (int k2 = 0; k2 < 4; k2++) {
            #pragma unroll
            for (int fj = 0; fj < 8; fj++) {
                int bw = (fj * 8 + g) * 36 + k2 * 8 + t;
                uint32_t vhf[2] = { Vhw[bw], Vhw[bw + 4] };
                uint32_t vlf[2] = { Vlw[bw], Vlw[bw + 4] };
                mma16816h(o[fj], ph[k2], vhf);
                mma16816h(o[fj], ph[k2], vlf);
            }
        }
        __syncthreads();
    }

    // write normalized output (bf16 hi/lo for out-proj)
    float inv0 = 1.0f / lrun[0];
    float inv1 = 1.0f / lrun[1];
    size_t off0 = ((size_t)bb * S_ + r0) * D_ + hh * HD_;
    size_t off1 = ((size_t)bb * S_ + r1) * D_ + hh * HD_;
    #pragma unroll
    for (int fj = 0; fj < 8; fj++) {
        int cl = fj * 8 + 2 * t;
        uint32_t hw, lw;
        split2(o[fj][0] * inv0, o[fj][1] * inv0, hw, lw);
        *(uint32_t*)&g_ah[off0 + cl] = hw;
        *(uint32_t*)&g_al[off0 + cl] = lw;
        split2(o[fj][2] * inv1, o[fj][3] * inv1, hw, lw);
        *(uint32_t*)&g_ah[off1 + cl] = hw;
        *(uint32_t*)&g_al[off1 + cl] = lw;
    }
}

// ---------------------------------------------------------------------------
extern "C" void kernel_launch(void* const* d_in, const int* in_sizes, int n_in,
                              void* d_out, int out_size)
{
    const float* query = (const float*)d_in[0];
    const float* key_  = (const float*)d_in[1];
    const float* value = (const float*)d_in[2];
    // d_in[3] = mask (tril) — handled analytically as causal
    const float* Wq = (const float*)d_in[4];
    const float* bq = (const float*)d_in[5];
    const float* Wk = (const float*)d_in[6];
    const float* bk = (const float*)d_in[7];
    const float* Wv = (const float*)d_in[8];
    const float* bv = (const float*)d_in[9];
    const float* Wo = (const float*)d_in[10];
    const float* bo = (const float*)d_in[11];
    float* out = (float*)d_out;

    cudaFuncSetAttribute(proj_qkv,    cudaFuncAttributeMaxDynamicSharedMemorySize, 2 * GSTG * 4);
    cudaFuncSetAttribute(proj_out,    cudaFuncAttributeMaxDynamicSharedMemorySize, 2 * GSTG * 4);
    cudaFuncSetAttribute(attn_kernel, cudaFuncAttributeMaxDynamicSharedMemorySize, 2 * ASTG * 4);

    split_acts<<<dim3(512, 3), 256>>>(query, key_, value);
    split_wts<<<dim3(64, 4), 256>>>(Wq, Wk, Wv, Wo);

    dim3 gproj(D_ / 128, MROWS / 128, 3);
    proj_qkv<<<gproj, 256, 2 * GSTG * 4>>>(bq, bk, bv);

    dim3 gattn(S_ / 64, B_ * H_);
    attn_kernel<<<gattn, 128, 2 * ASTG * 4>>>();

    dim3 gout(D_ / 128, MROWS / 128);
    proj_out<<<gout, 256, 2 * GSTG * 4>>>(bo, out);
}

// round 5
// speedup vs baseline: 5.8057x; 1.4822x over previous
#include <cuda_runtime.h>
#include <cuda_bf16.h>
#include <cuda_fp16.h>
#include <stdint.h>

#define B_  2
#define S_  4096
#define D_  768
#define H_  12
#define HD_ 64
#define MROWS 8192
#define NELEM (B_*H_*S_*HD_)

// activations pre-split fp16 hi/lo; weights single fp16
__device__ __half g_xqh[MROWS*D_], g_xql[MROWS*D_];
__device__ __half g_xkh[MROWS*D_], g_xkl[MROWS*D_];
__device__ __half g_xvh[MROWS*D_], g_xvl[MROWS*D_];
__device__ __half g_wqh[D_*D_], g_wkh[D_*D_], g_wvh[D_*D_], g_woh[D_*D_];
// projected Q/K: [b][h][s][hd] fp16 (Q pre-scaled by 0.125*log2e); V transposed [b][h][hd][s] fp16
__device__ __half g_qh[NELEM], g_kh[NELEM], g_vth[NELEM];
// attention output fp16 hi/lo [b][s][d]
__device__ __half g_ah[MROWS*D_], g_al[MROWS*D_];

// ---------------------------------------------------------------------------
__device__ __forceinline__ uint32_t pack_h2(float x0, float x1) {
    uint32_t r;
    asm("cvt.rn.f16x2.f32 %0, %1, %2;" : "=r"(r) : "f"(x1), "f"(x0));
    return r;
}
__device__ __forceinline__ void split2h(float x0, float x1, uint32_t& hi, uint32_t& lo) {
    __half h0 = __float2half_rn(x0);
    __half h1 = __float2half_rn(x1);
    hi = ((uint32_t)__half_as_ushort(h1) << 16) | (uint32_t)__half_as_ushort(h0);
    lo = pack_h2(x0 - __half2float(h0), x1 - __half2float(h1));
}
__device__ __forceinline__ void mma16816h(float (&c)[4], const uint32_t (&a)[4],
                                          const uint32_t (&b)[2]) {
    asm volatile(
        "mma.sync.aligned.m16n8k16.row.col.f32.f16.f16.f32 "
        "{%0,%1,%2,%3}, {%4,%5,%6,%7}, {%8,%9}, {%0,%1,%2,%3};\n"
        : "+f"(c[0]), "+f"(c[1]), "+f"(c[2]), "+f"(c[3])
        : "r"(a[0]), "r"(a[1]), "r"(a[2]), "r"(a[3]), "r"(b[0]), "r"(b[1]));
}
__device__ __forceinline__ uint32_t smem_u32(const void* p) {
    uint32_t a;
    asm("{ .reg .u64 t; cvta.to.shared.u64 t, %1; cvt.u32.u64 %0, t; }" : "=r"(a) : "l"(p));
    return a;
}
__device__ __forceinline__ void cp16(uint32_t d, const void* s) {
    asm volatile("cp.async.ca.shared.global [%0], [%1], 16;" :: "r"(d), "l"(s));
}
__device__ __forceinline__ void cp_commit() { asm volatile("cp.async.commit_group;"); }
template<int N> __device__ __forceinline__ void cp_wait() {
    asm volatile("cp.async.wait_group %0;" :: "n"(N));
}

// ---------------------------------------------------------------------------
// prep: split activations fp16 hi/lo; weights -> single fp16
// ---------------------------------------------------------------------------
__global__ void split_acts(const float* __restrict__ q, const float* __restrict__ k,
                           const float* __restrict__ v) {
    int z = blockIdx.y;
    const float* src = (z == 0) ? q : (z == 1) ? k : v;
    __half* h = (z == 0) ? g_xqh : (z == 1) ? g_xkh : g_xvh;
    __half* l = (z == 0) ? g_xql : (z == 1) ? g_xkl : g_xvl;
    int n4 = MROWS * D_ / 4;
    for (int i = blockIdx.x * blockDim.x + threadIdx.x; i < n4;
         i += gridDim.x * blockDim.x) {
        float4 v4 = ((const float4*)src)[i];
        uint32_t h0, l0, h1, l1;
        split2h(v4.x, v4.y, h0, l0);
        split2h(v4.z, v4.w, h1, l1);
        uint2 hw; hw.x = h0; hw.y = h1;
        uint2 lw; lw.x = l0; lw.y = l1;
        ((uint2*)h)[i] = hw;
        ((uint2*)l)[i] = lw;
    }
}

__global__ void split_wts(const float* __restrict__ wq, const float* __restrict__ wk,
                          const float* __restrict__ wv, const float* __restrict__ wo) {
    int z = blockIdx.y;
    const float* src = (z == 0) ? wq : (z == 1) ? wk : (z == 2) ? wv : wo;
    __half* h = (z == 0) ? g_wqh : (z == 1) ? g_wkh : (z == 2) ? g_wvh : g_woh;
    int n4 = D_ * D_ / 4;
    for (int i = blockIdx.x * blockDim.x + threadIdx.x; i < n4;
         i += gridDim.x * blockDim.x) {
        float4 v4 = ((const float4*)src)[i];
        uint2 hw;
        hw.x = pack_h2(v4.x, v4.y);
        hw.y = pack_h2(v4.z, v4.w);
        ((uint2*)h)[i] = hw;
    }
}

// ---------------------------------------------------------------------------
// GEMM: C = X @ W^T + bias; X fp16 hi/lo, W fp16 single (fp16x2 scheme).
// 128x128x32 tiles, 256 thr = 8 warps (4m x 2n). cp.async double-buffered.
// emode 0: Q (scale 0.125*log2e) head-split fp16; 1: K head-split fp16;
// 2: V transposed fp16; 3: fp32 row-major out.
// Stage words: Ah[2560] Al[2560] Bh[2560]; row stride 20 words.
// ---------------------------------------------------------------------------
#define GSTG 7680

__device__ __forceinline__ void gemm_core(
    const __half* __restrict__ Xh, const __half* __restrict__ Xl,
    const __half* __restrict__ Wh,
    const float* __restrict__ bias, float osc, int emode,
    __half* __restrict__ outh, float* __restrict__ outf)
{
    extern __shared__ uint32_t sm[];
    const uint32_t smb = smem_u32(sm);

    const int tid  = threadIdx.x;
    const int lane = tid & 31;
    const int warp = tid >> 5;
    const int wm = warp >> 1, wn = warp & 1;
    const int g = lane >> 2, t = lane & 3;
    const int m0 = blockIdx.y * 128;
    const int n0 = blockIdx.x * 128;

    auto issue = [&](int kt, int s) {
        int k0 = kt * 32;
        #pragma unroll
        for (int p = 0; p < 2; p++) {
            int idx = p * 256 + tid;
            int r = idx >> 2, c8 = (idx & 3) * 8;
            uint32_t dst = smb + (uint32_t)((s * GSTG + r * 20 + (c8 >> 1)) * 4);
            size_t ao = (size_t)(m0 + r) * D_ + k0 + c8;
            size_t bo = (size_t)(n0 + r) * D_ + k0 + c8;
            cp16(dst,            Xh + ao);
            cp16(dst + 2560 * 4, Xl + ao);
            cp16(dst + 5120 * 4, Wh + bo);
        }
        cp_commit();
    };

    float c[2][8][4];
    #pragma unroll
    for (int fi = 0; fi < 2; fi++)
        #pragma unroll
        for (int fj = 0; fj < 8; fj++)
            #pragma unroll
            for (int e = 0; e < 4; e++) c[fi][fj][e] = 0.0f;

    issue(0, 0);

    for (int kt = 0; kt < 24; kt++) {
        if (kt < 23) { issue(kt + 1, (kt + 1) & 1); cp_wait<1>(); }
        else         { cp_wait<0>(); }
        __syncthreads();

        const uint32_t* Ah = sm + (kt & 1) * GSTG;
        const uint32_t* Al = Ah + 2560;
        const uint32_t* Bh = Ah + 5120;

        #pragma unroll
        for (int ks = 0; ks < 2; ks++) {
            uint32_t ah[2][4], al[2][4];
            #pragma unroll
            for (int fi = 0; fi < 2; fi++) {
                int base = (wm * 32 + fi * 16 + g) * 20 + ks * 8 + t;
                ah[fi][0] = Ah[base];
                ah[fi][1] = Ah[base + 8 * 20];
                ah[fi][2] = Ah[base + 4];
                ah[fi][3] = Ah[base + 8 * 20 + 4];
                al[fi][0] = Al[base];
                al[fi][1] = Al[base + 8 * 20];
                al[fi][2] = Al[base + 4];
                al[fi][3] = Al[base + 8 * 20 + 4];
            }
            #pragma unroll
            for (int fj = 0; fj < 8; fj++) {
                int bw = (wn * 64 + fj * 8 + g) * 20 + ks * 8 + t;
                uint32_t bhf[2] = { Bh[bw], Bh[bw + 4] };
                #pragma unroll
                for (int fi = 0; fi < 2; fi++) {
                    mma16816h(c[fi][fj], ah[fi], bhf);
                    mma16816h(c[fi][fj], al[fi], bhf);
                }
            }
        }
        __syncthreads();
    }

    #pragma unroll
    for (int fi = 0; fi < 2; fi++) {
        #pragma unroll
        for (int rr = 0; rr < 2; rr++) {
            int m = m0 + wm * 32 + fi * 16 + g + rr * 8;
            #pragma unroll
            for (int fj = 0; fj < 8; fj++) {
                int n = n0 + wn * 64 + fj * 8 + 2 * t;
                float v0 = c[fi][fj][rr * 2 + 0] + bias[n];
                float v1 = c[fi][fj][rr * 2 + 1] + bias[n + 1];
                if (emode <= 1) {
                    v0 *= osc; v1 *= osc;
                    int bb = m >> 12, ss = m & 4095;
                    int hh = n >> 6,  hd = n & 63;
                    size_t off = (((size_t)bb * H_ + hh) * S_ + ss) * HD_ + hd;
                    *(uint32_t*)&outh[off] = pack_h2(v0, v1);
                } else if (emode == 2) {
                    int bb = m >> 12, ss = m & 4095;
                    int hh = n >> 6,  hd = n & 63;
                    size_t base = (((size_t)bb * H_ + hh) * HD_ + hd) * S_ + ss;
                    outh[base]      = __float2half_rn(v0);
                    outh[base + S_] = __float2half_rn(v1);
                } else {
                    float2 o2; o2.x = v0; o2.y = v1;
                    *(float2*)&outf[(size_t)m * D_ + n] = o2;
                }
            }
        }
    }
}

__global__ void __launch_bounds__(256, 2) proj_qkv(
    const float* __restrict__ bq, const float* __restrict__ bk, const float* __restrict__ bv)
{
    int z = blockIdx.z;
    const __half* Xh = (z == 0) ? g_xqh : (z == 1) ? g_xkh : g_xvh;
    const __half* Xl = (z == 0) ? g_xql : (z == 1) ? g_xkl : g_xvl;
    const __half* Wh = (z == 0) ? g_wqh : (z == 1) ? g_wkh : g_wvh;
    const float* bias = (z == 0) ? bq : (z == 1) ? bk : bv;
    __half* oh = (z == 0) ? g_qh : (z == 1) ? g_kh : g_vth;
    float osc = (z == 0) ? (0.125f * 1.44269504f) : 1.0f;   // Q: fold 1/8 and log2(e)
    gemm_core(Xh, Xl, Wh, bias, osc, z, oh, nullptr);
}

__global__ void __launch_bounds__(256, 2) proj_out(
    const float* __restrict__ bo, float* __restrict__ out)
{
    gemm_core(g_ah, g_al, g_woh, bo, 1.0f, 3, nullptr, out);
}

// ---------------------------------------------------------------------------
// Flash attention, causal, single-fp16 MMA. Scores in log2 units
// (Q pre-scaled by 0.125*log2e). P via h2exp2; row-sum l via ones-column in V
// (PV MMA fj=8). 64 q-rows/CTA, 64-key tiles, 128 thr = 4 warps x 16 rows.
// Stage words: K 64 rows x 36; V 72 rows x 36 (rows 64..71 const: row64=1.0).
// ---------------------------------------------------------------------------
#define ASTG 4896   // (64+72)*36 words per stage

__global__ void __launch_bounds__(128, 3) attn_kernel()
{
    extern __shared__ uint32_t sm[];
    const uint32_t smb = smem_u32(sm);

    const int tid  = threadIdx.x;
    const int lane = tid & 31;
    const int wm   = tid >> 5;
    const int g    = lane >> 2;
    const int t    = lane & 3;
    const int qt = gridDim.x - 1 - blockIdx.x;   // heavy CTAs first
    const int bh = blockIdx.y;
    const int bb = bh / H_;
    const int hh = bh % H_;
    const int q0 = qt * 64;

    auto issue = [&](int jt, int s) {
        int k0 = jt * 64;
        #pragma unroll
        for (int p = 0; p < 4; p++) {
            int idx = p * 128 + tid;
            int row = idx >> 3, c8 = (idx & 7) * 8;
            uint32_t dstK = smb + (uint32_t)((s * ASTG + row * 36 + (c8 >> 1)) * 4);
            uint32_t dstV = dstK + 2304 * 4;
            cp16(dstK, g_kh  + ((size_t)bh * S_ + k0 + row) * HD_ + c8);
            cp16(dstV, g_vth + ((size_t)bh * HD_ + row) * S_ + k0 + c8);
        }
        cp_commit();
    };

    issue(0, 0);

    // constant V rows 64..71 (row 64 = ones -> l column), both stages
    #pragma unroll
    for (int p = 0; p < 4; p++) {
        int idx = p * 128 + tid;          // 0..511
        int s   = idx >> 8;               // stage
        int rem = idx & 255;
        int row = 64 + (rem >> 5);        // 64..71
        int w   = rem & 31;
        sm[s * ASTG + 2304 + row * 36 + w] = (row == 64) ? 0x3C003C00u : 0u;
    }

    // Q fragments fp16
    uint32_t qh[4][4];
    {
        const __half* qb = g_qh + ((size_t)bh * S_ + q0 + wm * 16) * HD_;
        #pragma unroll
        for (int kt = 0; kt < 4; kt++) {
            int kc = kt * 16 + 2 * t;
            qh[kt][0] = *(const uint32_t*)&qb[(size_t)g * HD_ + kc];
            qh[kt][1] = *(const uint32_t*)&qb[(size_t)(g + 8) * HD_ + kc];
            qh[kt][2] = *(const uint32_t*)&qb[(size_t)g * HD_ + kc + 8];
            qh[kt][3] = *(const uint32_t*)&qb[(size_t)(g + 8) * HD_ + kc + 8];
        }
    }

    float o[9][4];                 // fj=8 column group holds l (ones-column)
    float mrun[2];
    mrun[0] = mrun[1] = -1e30f;
    #pragma unroll
    for (int fj = 0; fj < 9; fj++)
        #pragma unroll
        for (int e = 0; e < 4; e++) o[fj][e] = 0.0f;

    const int r0 = q0 + wm * 16 + g;
    const int r1 = r0 + 8;

    for (int jt = 0; jt <= qt; jt++) {
        const int k0 = jt * 64;
        if (jt < qt) { issue(jt + 1, (jt + 1) & 1); cp_wait<1>(); }
        else         { cp_wait<0>(); }
        __syncthreads();

        const uint32_t* Khw = sm + (jt & 1) * ASTG;
        const uint32_t* Vhw = Khw + 2304;

        // S = Q @ K^T (log2 units)
        float s[8][4];
        #pragma unroll
        for (int fj = 0; fj < 8; fj++)
            #pragma unroll
            for (int e = 0; e < 4; e++) s[fj][e] = 0.0f;

        #pragma unroll
        for (int kt = 0; kt < 4; kt++) {
            #pragma unroll
            for (int fj = 0; fj < 8; fj++) {
                int bw = (fj * 8 + g) * 36 + kt * 8 + t;
                uint32_t kf[2] = { Khw[bw], Khw[bw + 4] };
                mma16816h(s[fj], qh[kt], kf);
            }
        }

        if (jt == qt) {
            #pragma unroll
            for (int fj = 0; fj < 8; fj++) {
                int cn = k0 + fj * 8 + 2 * t;
                if (cn     > r0) s[fj][0] = -1e30f;
                if (cn + 1 > r0) s[fj][1] = -1e30f;
                if (cn     > r1) s[fj][2] = -1e30f;
                if (cn + 1 > r1) s[fj][3] = -1e30f;
            }
        }

        // online softmax: max + rescale (fp32), P = 2^(s-m) in f16x2
        float mnew2[2];
        #pragma unroll
        for (int r = 0; r < 2; r++) {
            float mx = -1e30f;
            #pragma unroll
            for (int fj = 0; fj < 8; fj++)
                mx = fmaxf(mx, fmaxf(s[fj][2 * r], s[fj][2 * r + 1]));
            mx = fmaxf(mx, __shfl_xor_sync(0xffffffffu, mx, 1));
            mx = fmaxf(mx, __shfl_xor_sync(0xffffffffu, mx, 2));
            float mnew  = fmaxf(mrun[r], mx);
            float scale = exp2f(mrun[r] - mnew);
            mrun[r] = mnew;
            mnew2[r] = mnew;
            #pragma unroll
            for (int fj = 0; fj < 9; fj++) {
                o[fj][2 * r]     *= scale;
                o[fj][2 * r + 1] *= scale;
            }
        }

        __half2 m20 = __float2half2_rn(mnew2[0]);
        __half2 m21 = __float2half2_rn(mnew2[1]);
        uint32_t ph[4][4];
        #pragma unroll
        for (int k2 = 0; k2 < 4; k2++) {
            __half2 a0 = __floats2half2_rn(s[2 * k2][0],     s[2 * k2][1]);
            __half2 a1 = __floats2half2_rn(s[2 * k2][2],     s[2 * k2][3]);
            __half2 a2 = __floats2half2_rn(s[2 * k2 + 1][0], s[2 * k2 + 1][1]);
            __half2 a3 = __floats2half2_rn(s[2 * k2 + 1][2], s[2 * k2 + 1][3]);
            __half2 p0 = h2exp2(__hsub2(a0, m20));
            __half2 p1 = h2exp2(__hsub2(a1, m21));
            __half2 p2 = h2exp2(__hsub2(a2, m20));
            __half2 p3 = h2exp2(__hsub2(a3, m21));
            ph[k2][0] = *(uint32_t*)&p0;
            ph[k2][1] = *(uint32_t*)&p1;
            ph[k2][2] = *(uint32_t*)&p2;
            ph[k2][3] = *(uint32_t*)&p3;
        }

        // O(+l) += P @ [V | 1]
        #pragma unroll
        for (int k2 = 0; k2 < 4; k2++) {
            #pragma unroll
            for (int fj = 0; fj < 9; fj++) {
                int bw = (fj * 8 + g) * 36 + k2 * 8 + t;
                uint32_t vf[2] = { Vhw[bw], Vhw[bw + 4] };
                mma16816h(o[fj], ph[k2], vf);
            }
        }
        __syncthreads();
    }

    // l lives in o[8][0]/o[8][2] of the t=0 thread of each quad
    int src = lane & 28;
    float l0 = __shfl_sync(0xffffffffu, o[8][0], src);
    float l1 = __shfl_sync(0xffffffffu, o[8][2], src);
    float inv0 = 1.0f / l0;
    float inv1 = 1.0f / l1;
    size_t off0 = ((size_t)bb * S_ + r0) * D_ + hh * HD_;
    size_t off1 = ((size_t)bb * S_ + r1) * D_ + hh * HD_;
    #pragma unroll
    for (int fj = 0; fj < 8; fj++) {
        int cl = fj * 8 + 2 * t;
        uint32_t hw, lw;
        split2h(o[fj][0] * inv0, o[fj][1] * inv0, hw, lw);
        *(uint32_t*)&g_ah[off0 + cl] = hw;
        *(uint32_t*)&g_al[off0 + cl] = lw;
        split2h(o[fj][2] * inv1, o[fj][3] * inv1, hw, lw);
        *(uint32_t*)&g_ah[off1 + cl] = hw;
        *(uint32_t*)&g_al[off1 + cl] = lw;
    }
}

// ---------------------------------------------------------------------------
extern "C" void kernel_launch(void* const* d_in, const int* in_sizes, int n_in,
                              void* d_out, int out_size)
{
    const float* query = (const float*)d_in[0];
    const float* key_  = (const float*)d_in[1];
    const float* value = (const float*)d_in[2];
    // d_in[3] = mask (tril) — handled analytically as causal
    const float* Wq = (const float*)d_in[4];
    const float* bq = (const float*)d_in[5];
    const float* Wk = (const float*)d_in[6];
    const float* bk = (const float*)d_in[7];
    const float* Wv = (const float*)d_in[8];
    const float* bv = (const float*)d_in[9];
    const float* Wo = (const float*)d_in[10];
    const float* bo = (const float*)d_in[11];
    float* out = (float*)d_out;

    cudaFuncSetAttribute(proj_qkv,    cudaFuncAttributeMaxDynamicSharedMemorySize, 2 * GSTG * 4);
    cudaFuncSetAttribute(proj_out,    cudaFuncAttributeMaxDynamicSharedMemorySize, 2 * GSTG * 4);
    cudaFuncSetAttribute(attn_kernel, cudaFuncAttributeMaxDynamicSharedMemorySize, 2 * ASTG * 4);

    split_acts<<<dim3(512, 3), 256>>>(query, key_, value);
    split_wts<<<dim3(64, 4), 256>>>(Wq, Wk, Wv, Wo);

    dim3 gproj(D_ / 128, MROWS / 128, 3);
    proj_qkv<<<gproj, 256, 2 * GSTG * 4>>>(bq, bk, bv);

    dim3 gattn(S_ / 64, B_ * H_);
    attn_kernel<<<gattn, 128, 2 * ASTG * 4>>>();

    dim3 gout(D_ / 128, MROWS / 128);
    proj_out<<<gout, 256, 2 * GSTG * 4>>>(bo, out);
}

// round 6
// speedup vs baseline: 6.5451x; 1.1274x over previous
#include <cuda_runtime.h>
#include <cuda_bf16.h>
#include <cuda_fp16.h>
#include <stdint.h>

#define B_  2
#define S_  4096
#define D_  768
#define H_  12
#define HD_ 64
#define MROWS 8192
#define NELEM (B_*H_*S_*HD_)

// activations pre-split fp16 hi/lo; weights single fp16
__device__ __half g_xqh[MROWS*D_], g_xql[MROWS*D_];
__device__ __half g_xkh[MROWS*D_], g_xkl[MROWS*D_];
__device__ __half g_xvh[MROWS*D_], g_xvl[MROWS*D_];
__device__ __half g_wqh[D_*D_], g_wkh[D_*D_], g_wvh[D_*D_], g_woh[D_*D_];
// projected Q/K: [b][h][s][hd] fp16 (Q pre-scaled by 0.125*log2e); V transposed [b][h][hd][s] fp16
__device__ __half g_qh[NELEM], g_kh[NELEM], g_vth[NELEM];
// attention output fp16 hi/lo [b][s][d]
__device__ __half g_ah[MROWS*D_], g_al[MROWS*D_];

// ---------------------------------------------------------------------------
__device__ __forceinline__ uint32_t pack_h2(float x0, float x1) {
    uint32_t r;
    asm("cvt.rn.f16x2.f32 %0, %1, %2;" : "=r"(r) : "f"(x1), "f"(x0));
    return r;
}
__device__ __forceinline__ void split2h(float x0, float x1, uint32_t& hi, uint32_t& lo) {
    __half h0 = __float2half_rn(x0);
    __half h1 = __float2half_rn(x1);
    hi = ((uint32_t)__half_as_ushort(h1) << 16) | (uint32_t)__half_as_ushort(h0);
    lo = pack_h2(x0 - __half2float(h0), x1 - __half2float(h1));
}
__device__ __forceinline__ void mma16816h(float (&c)[4], const uint32_t (&a)[4],
                                          uint32_t b0, uint32_t b1) {
    asm volatile(
        "mma.sync.aligned.m16n8k16.row.col.f32.f16.f16.f32 "
        "{%0,%1,%2,%3}, {%4,%5,%6,%7}, {%8,%9}, {%0,%1,%2,%3};\n"
        : "+f"(c[0]), "+f"(c[1]), "+f"(c[2]), "+f"(c[3])
        : "r"(a[0]), "r"(a[1]), "r"(a[2]), "r"(a[3]), "r"(b0), "r"(b1));
}
__device__ __forceinline__ void ldsm4(uint32_t (&r)[4], uint32_t addr) {
    asm volatile("ldmatrix.sync.aligned.m8n8.x4.shared.b16 {%0,%1,%2,%3}, [%4];"
        : "=r"(r[0]), "=r"(r[1]), "=r"(r[2]), "=r"(r[3]) : "r"(addr));
}
__device__ __forceinline__ uint32_t smem_u32(const void* p) {
    uint32_t a;
    asm("{ .reg .u64 t; cvta.to.shared.u64 t, %1; cvt.u32.u64 %0, t; }" : "=r"(a) : "l"(p));
    return a;
}
__device__ __forceinline__ void cp16(uint32_t d, const void* s) {
    asm volatile("cp.async.ca.shared.global [%0], [%1], 16;" :: "r"(d), "l"(s));
}
__device__ __forceinline__ void cp_commit() { asm volatile("cp.async.commit_group;"); }
template<int N> __device__ __forceinline__ void cp_wait() {
    asm volatile("cp.async.wait_group %0;" :: "n"(N));
}

// ---------------------------------------------------------------------------
// prep kernels
// ---------------------------------------------------------------------------
__global__ void split_acts(const float* __restrict__ q, const float* __restrict__ k,
                           const float* __restrict__ v) {
    int z = blockIdx.y;
    const float* src = (z == 0) ? q : (z == 1) ? k : v;
    __half* h = (z == 0) ? g_xqh : (z == 1) ? g_xkh : g_xvh;
    __half* l = (z == 0) ? g_xql : (z == 1) ? g_xkl : g_xvl;
    int n4 = MROWS * D_ / 4;
    for (int i = blockIdx.x * blockDim.x + threadIdx.x; i < n4;
         i += gridDim.x * blockDim.x) {
        float4 v4 = ((const float4*)src)[i];
        uint32_t h0, l0, h1, l1;
        split2h(v4.x, v4.y, h0, l0);
        split2h(v4.z, v4.w, h1, l1);
        uint2 hw; hw.x = h0; hw.y = h1;
        uint2 lw; lw.x = l0; lw.y = l1;
        ((uint2*)h)[i] = hw;
        ((uint2*)l)[i] = lw;
    }
}

__global__ void split_wts(const float* __restrict__ wq, const float* __restrict__ wk,
                          const float* __restrict__ wv, const float* __restrict__ wo) {
    int z = blockIdx.y;
    const float* src = (z == 0) ? wq : (z == 1) ? wk : (z == 2) ? wv : wo;
    __half* h = (z == 0) ? g_wqh : (z == 1) ? g_wkh : (z == 2) ? g_wvh : g_woh;
    int n4 = D_ * D_ / 4;
    for (int i = blockIdx.x * blockDim.x + threadIdx.x; i < n4;
         i += gridDim.x * blockDim.x) {
        float4 v4 = ((const float4*)src)[i];
        uint2 hw;
        hw.x = pack_h2(v4.x, v4.y);
        hw.y = pack_h2(v4.z, v4.w);
        ((uint2*)h)[i] = hw;
    }
}

// ---------------------------------------------------------------------------
// GEMM: C = X @ W^T + bias; X fp16 hi/lo, W fp16 single. 128x128x32 tiles,
// 256 thr = 8 warps (4m x 2n). cp.async double-buffered, ldmatrix fragments.
// Stage words: Ah[2560] Al[2560] Bh[2560]; row stride 20 words (80B).
// ---------------------------------------------------------------------------
#define GSTG 7680

__device__ __forceinline__ void gemm_core(
    const __half* __restrict__ Xh, const __half* __restrict__ Xl,
    const __half* __restrict__ Wh,
    const float* __restrict__ bias, float osc, int emode,
    __half* __restrict__ outh, float* __restrict__ outf)
{
    extern __shared__ uint32_t sm[];
    const uint32_t smb = smem_u32(sm);

    const int tid  = threadIdx.x;
    const int lane = tid & 31;
    const int warp = tid >> 5;
    const int wm = warp >> 1, wn = warp & 1;
    const int g = lane >> 2, t = lane & 3;
    const int m0 = blockIdx.y * 128;
    const int n0 = blockIdx.x * 128;

    // ldmatrix lane offsets (bytes) within a stage
    const uint32_t la = (uint32_t)(((wm * 32 + (lane & 7) + ((lane >> 3) & 1) * 8) * 20) * 4
                                   + ((lane >> 4) & 1) * 16);
    const uint32_t lb = (uint32_t)(((wn * 64 + ((lane >> 4) & 1) * 8 + (lane & 7)) * 20) * 4
                                   + ((lane >> 3) & 1) * 16);

    auto issue = [&](int kt, int s) {
        int k0 = kt * 32;
        #pragma unroll
        for (int p = 0; p < 2; p++) {
            int idx = p * 256 + tid;
            int r = idx >> 2, c8 = (idx & 3) * 8;
            uint32_t dst = smb + (uint32_t)((s * GSTG + r * 20 + (c8 >> 1)) * 4);
            size_t ao = (size_t)(m0 + r) * D_ + k0 + c8;
            size_t bo = (size_t)(n0 + r) * D_ + k0 + c8;
            cp16(dst,            Xh + ao);
            cp16(dst + 2560 * 4, Xl + ao);
            cp16(dst + 5120 * 4, Wh + bo);
        }
        cp_commit();
    };

    float c[2][8][4];
    #pragma unroll
    for (int fi = 0; fi < 2; fi++)
        #pragma unroll
        for (int fj = 0; fj < 8; fj++)
            #pragma unroll
            for (int e = 0; e < 4; e++) c[fi][fj][e] = 0.0f;

    issue(0, 0);

    for (int kt = 0; kt < 24; kt++) {
        if (kt < 23) { issue(kt + 1, (kt + 1) & 1); cp_wait<1>(); }
        else         { cp_wait<0>(); }
        __syncthreads();

        uint32_t Ab = smb + (uint32_t)((kt & 1) * GSTG * 4);
        uint32_t Lb = Ab + 2560 * 4;
        uint32_t Bb = Ab + 5120 * 4;

        #pragma unroll
        for (int ks = 0; ks < 2; ks++) {
            uint32_t ah[2][4], al[2][4];
            #pragma unroll
            for (int fi = 0; fi < 2; fi++) {
                ldsm4(ah[fi], Ab + la + (uint32_t)(fi * 16 * 20 * 4 + ks * 32));
                ldsm4(al[fi], Lb + la + (uint32_t)(fi * 16 * 20 * 4 + ks * 32));
            }
            #pragma unroll
            for (int p = 0; p < 4; p++) {
                uint32_t bf[4];
                ldsm4(bf, Bb + lb + (uint32_t)(p * 16 * 20 * 4 + ks * 32));
                #pragma unroll
                for (int fi = 0; fi < 2; fi++) {
                    mma16816h(c[fi][2 * p],     ah[fi], bf[0], bf[1]);
                    mma16816h(c[fi][2 * p],     al[fi], bf[0], bf[1]);
                    mma16816h(c[fi][2 * p + 1], ah[fi], bf[2], bf[3]);
                    mma16816h(c[fi][2 * p + 1], al[fi], bf[2], bf[3]);
                }
            }
        }
        __syncthreads();
    }

    #pragma unroll
    for (int fi = 0; fi < 2; fi++) {
        #pragma unroll
        for (int rr = 0; rr < 2; rr++) {
            int m = m0 + wm * 32 + fi * 16 + g + rr * 8;
            #pragma unroll
            for (int fj = 0; fj < 8; fj++) {
                int n = n0 + wn * 64 + fj * 8 + 2 * t;
                float v0 = c[fi][fj][rr * 2 + 0] + bias[n];
                float v1 = c[fi][fj][rr * 2 + 1] + bias[n + 1];
                if (emode <= 1) {
                    v0 *= osc; v1 *= osc;
                    int bb = m >> 12, ss = m & 4095;
                    int hh = n >> 6,  hd = n & 63;
                    size_t off = (((size_t)bb * H_ + hh) * S_ + ss) * HD_ + hd;
                    *(uint32_t*)&outh[off] = pack_h2(v0, v1);
                } else if (emode == 2) {
                    int bb = m >> 12, ss = m & 4095;
                    int hh = n >> 6,  hd = n & 63;
                    size_t base = (((size_t)bb * H_ + hh) * HD_ + hd) * S_ + ss;
                    outh[base]      = __float2half_rn(v0);
                    outh[base + S_] = __float2half_rn(v1);
                } else {
                    float2 o2; o2.x = v0; o2.y = v1;
                    *(float2*)&outf[(size_t)m * D_ + n] = o2;
                }
            }
        }
    }
}

__global__ void __launch_bounds__(256, 2) proj_qkv(
    const float* __restrict__ bq, const float* __restrict__ bk, const float* __restrict__ bv)
{
    int z = blockIdx.z;
    const __half* Xh = (z == 0) ? g_xqh : (z == 1) ? g_xkh : g_xvh;
    const __half* Xl = (z == 0) ? g_xql : (z == 1) ? g_xkl : g_xvl;
    const __half* Wh = (z == 0) ? g_wqh : (z == 1) ? g_wkh : g_wvh;
    const float* bias = (z == 0) ? bq : (z == 1) ? bk : bv;
    __half* oh = (z == 0) ? g_qh : (z == 1) ? g_kh : g_vth;
    float osc = (z == 0) ? (0.125f * 1.44269504f) : 1.0f;   // Q: fold 1/8 and log2(e)
    gemm_core(Xh, Xl, Wh, bias, osc, z, oh, nullptr);
}

__global__ void __launch_bounds__(256, 2) proj_out(
    const float* __restrict__ bo, float* __restrict__ out)
{
    gemm_core(g_ah, g_al, g_woh, bo, 1.0f, 3, nullptr, out);
}

// ---------------------------------------------------------------------------
// Flash attention, causal, single-fp16 MMA, log2-domain softmax, l via
// constant ones B-fragment. 64 q-rows/CTA, 64-key tiles, 128 thr = 4 warps.
// Stage words: K 64x36, V 64x36 (V transposed [hd][seq]). ldmatrix fragments.
// ---------------------------------------------------------------------------
#define ASTG 4608   // words per stage

__global__ void __launch_bounds__(128, 3) attn_kernel()
{
    extern __shared__ uint32_t sm[];
    const uint32_t smb = smem_u32(sm);

    const int tid  = threadIdx.x;
    const int lane = tid & 31;
    const int wm   = tid >> 5;
    const int g    = lane >> 2;
    const int t    = lane & 3;
    const int qt = gridDim.x - 1 - blockIdx.x;   // heavy CTAs first
    const int bh = blockIdx.y;
    const int bb = bh / H_;
    const int hh = bh % H_;
    const int q0 = qt * 64;

    // ldmatrix lane offset (bytes): row = (lane>>4)*8 + (lane&7), khalf = (lane>>3)&1
    const uint32_t lk = (uint32_t)(((((lane >> 4) & 1) * 8 + (lane & 7)) * 36) * 4
                                   + ((lane >> 3) & 1) * 16);
    // constant ones-column B fragment (row n=0 of the block is 1.0)
    const uint32_t ones = (lane < 4) ? 0x3C003C00u : 0u;

    auto issue = [&](int jt, int s) {
        int k0 = jt * 64;
        #pragma unroll
        for (int p = 0; p < 4; p++) {
            int idx = p * 128 + tid;
            int row = idx >> 3, c8 = (idx & 7) * 8;
            uint32_t dstK = smb + (uint32_t)((s * ASTG + row * 36 + (c8 >> 1)) * 4);
            cp16(dstK,            g_kh  + ((size_t)bh * S_ + k0 + row) * HD_ + c8);
            cp16(dstK + 2304 * 4, g_vth + ((size_t)bh * HD_ + row) * S_ + k0 + c8);
        }
        cp_commit();
    };

    issue(0, 0);

    // Q fragments fp16
    uint32_t qh[4][4];
    {
        const __half* qb = g_qh + ((size_t)bh * S_ + q0 + wm * 16) * HD_;
        #pragma unroll
        for (int kt = 0; kt < 4; kt++) {
            int kc = kt * 16 + 2 * t;
            qh[kt][0] = *(const uint32_t*)&qb[(size_t)g * HD_ + kc];
            qh[kt][1] = *(const uint32_t*)&qb[(size_t)(g + 8) * HD_ + kc];
            qh[kt][2] = *(const uint32_t*)&qb[(size_t)g * HD_ + kc + 8];
            qh[kt][3] = *(const uint32_t*)&qb[(size_t)(g + 8) * HD_ + kc + 8];
        }
    }

    float o[9][4];                 // fj=8 group holds l (ones-column)
    float mrun[2];
    mrun[0] = mrun[1] = -1e30f;
    #pragma unroll
    for (int fj = 0; fj < 9; fj++)
        #pragma unroll
        for (int e = 0; e < 4; e++) o[fj][e] = 0.0f;

    const int r0 = q0 + wm * 16 + g;
    const int r1 = r0 + 8;

    for (int jt = 0; jt <= qt; jt++) {
        const int k0 = jt * 64;
        if (jt < qt) { issue(jt + 1, (jt + 1) & 1); cp_wait<1>(); }
        else         { cp_wait<0>(); }
        __syncthreads();

        uint32_t Kb = smb + (uint32_t)((jt & 1) * ASTG * 4) + lk;
        uint32_t Vb = Kb + 2304 * 4;

        // S = Q @ K^T (log2 units)
        float s[8][4];
        #pragma unroll
        for (int fj = 0; fj < 8; fj++)
            #pragma unroll
            for (int e = 0; e < 4; e++) s[fj][e] = 0.0f;

        #pragma unroll
        for (int kt = 0; kt < 4; kt++) {
            #pragma unroll
            for (int p = 0; p < 4; p++) {
                uint32_t kf[4];
                ldsm4(kf, Kb + (uint32_t)(p * 2304 + kt * 32));
                mma16816h(s[2 * p],     qh[kt], kf[0], kf[1]);
                mma16816h(s[2 * p + 1], qh[kt], kf[2], kf[3]);
            }
        }

        if (jt == qt) {
            #pragma unroll
            for (int fj = 0; fj < 8; fj++) {
                int cn = k0 + fj * 8 + 2 * t;
                if (cn     > r0) s[fj][0] = -1e30f;
                if (cn + 1 > r0) s[fj][1] = -1e30f;
                if (cn     > r1) s[fj][2] = -1e30f;
                if (cn + 1 > r1) s[fj][3] = -1e30f;
            }
        }

        // online softmax: max + rescale (fp32), P = 2^(s-m) in f16x2
        float mnew2[2];
        #pragma unroll
        for (int r = 0; r < 2; r++) {
            float mx = -1e30f;
            #pragma unroll
            for (int fj = 0; fj < 8; fj++)
                mx = fmaxf(mx, fmaxf(s[fj][2 * r], s[fj][2 * r + 1]));
            mx = fmaxf(mx, __shfl_xor_sync(0xffffffffu, mx, 1));
            mx = fmaxf(mx, __shfl_xor_sync(0xffffffffu, mx, 2));
            float mnew  = fmaxf(mrun[r], mx);
            float scale = exp2f(mrun[r] - mnew);
            mrun[r] = mnew;
            mnew2[r] = mnew;
            #pragma unroll
            for (int fj = 0; fj < 9; fj++) {
                o[fj][2 * r]     *= scale;
                o[fj][2 * r + 1] *= scale;
            }
        }

        __half2 m20 = __float2half2_rn(mnew2[0]);
        __half2 m21 = __float2half2_rn(mnew2[1]);
        uint32_t ph[4][4];
        #pragma unroll
        for (int k2 = 0; k2 < 4; k2++) {
            __half2 a0 = __floats2half2_rn(s[2 * k2][0],     s[2 * k2][1]);
            __half2 a1 = __floats2half2_rn(s[2 * k2][2],     s[2 * k2][3]);
            __half2 a2 = __floats2half2_rn(s[2 * k2 + 1][0], s[2 * k2 + 1][1]);
            __half2 a3 = __floats2half2_rn(s[2 * k2 + 1][2], s[2 * k2 + 1][3]);
            __half2 p0 = h2exp2(__hsub2(a0, m20));
            __half2 p1 = h2exp2(__hsub2(a1, m21));
            __half2 p2 = h2exp2(__hsub2(a2, m20));
            __half2 p3 = h2exp2(__hsub2(a3, m21));
            ph[k2][0] = *(uint32_t*)&p0;
            ph[k2][1] = *(uint32_t*)&p1;
            ph[k2][2] = *(uint32_t*)&p2;
            ph[k2][3] = *(uint32_t*)&p3;
        }

        // O(+l) += P @ [V | 1]
        #pragma unroll
        for (int k2 = 0; k2 < 4; k2++) {
            #pragma unroll
            for (int p = 0; p < 4; p++) {
                uint32_t vf[4];
                ldsm4(vf, Vb + (uint32_t)(p * 2304 + k2 * 32));
                mma16816h(o[2 * p],     ph[k2], vf[0], vf[1]);
                mma16816h(o[2 * p + 1], ph[k2], vf[2], vf[3]);
            }
            mma16816h(o[8], ph[k2], ones, ones);
        }
        __syncthreads();
    }

    // l lives in o[8][0]/o[8][2] of the t=0 thread of each quad
    int src = lane & 28;
    float l0 = __shfl_sync(0xffffffffu, o[8][0], src);
    float l1 = __shfl_sync(0xffffffffu, o[8][2], src);
    float inv0 = 1.0f / l0;
    float inv1 = 1.0f / l1;
    size_t off0 = ((size_t)bb * S_ + r0) * D_ + hh * HD_;
    size_t off1 = ((size_t)bb * S_ + r1) * D_ + hh * HD_;
    #pragma unroll
    for (int fj = 0; fj < 8; fj++) {
        int cl = fj * 8 + 2 * t;
        uint32_t hw, lw;
        split2h(o[fj][0] * inv0, o[fj][1] * inv0, hw, lw);
        *(uint32_t*)&g_ah[off0 + cl] = hw;
        *(uint32_t*)&g_al[off0 + cl] = lw;
        split2h(o[fj][2] * inv1, o[fj][3] * inv1, hw, lw);
        *(uint32_t*)&g_ah[off1 + cl] = hw;
        *(uint32_t*)&g_al[off1 + cl] = lw;
    }
}

// ---------------------------------------------------------------------------
extern "C" void kernel_launch(void* const* d_in, const int* in_sizes, int n_in,
                              void* d_out, int out_size)
{
    const float* query = (const float*)d_in[0];
    const float* key_  = (const float*)d_in[1];
    const float* value = (const float*)d_in[2];
    // d_in[3] = mask (tril) — handled analytically as causal
    const float* Wq = (const float*)d_in[4];
    const float* bq = (const float*)d_in[5];
    const float* Wk = (const float*)d_in[6];
    const float* bk = (const float*)d_in[7];
    const float* Wv = (const float*)d_in[8];
    const float* bv = (const float*)d_in[9];
    const float* Wo = (const float*)d_in[10];
    const float* bo = (const float*)d_in[11];
    float* out = (float*)d_out;

    cudaFuncSetAttribute(proj_qkv,    cudaFuncAttributeMaxDynamicSharedMemorySize, 2 * GSTG * 4);
    cudaFuncSetAttribute(proj_out,    cudaFuncAttributeMaxDynamicSharedMemorySize, 2 * GSTG * 4);
    cudaFuncSetAttribute(attn_kernel, cudaFuncAttributeMaxDynamicSharedMemorySize, 2 * ASTG * 4);

    split_acts<<<dim3(512, 3), 256>>>(query, key_, value);
    split_wts<<<dim3(64, 4), 256>>>(Wq, Wk, Wv, Wo);

    dim3 gproj(D_ / 128, MROWS / 128, 3);
    proj_qkv<<<gproj, 256, 2 * GSTG * 4>>>(bq, bk, bv);

    dim3 gattn(S_ / 64, B_ * H_);
    attn_kernel<<<gattn, 128, 2 * ASTG * 4>>>();

    dim3 gout(D_ / 128, MROWS / 128);
    proj_out<<<gout, 256, 2 * GSTG * 4>>>(bo, out);
}